// round 15
// baseline (speedup 1.0000x reference)
#include <cuda_runtime.h>
#include <math.h>
#include <cstdint>

#define NB    8
#define DIM   256
#define YD    4096
#define HH    8
#define INNER 512
#define WW    256
#define ASCALE 0.125f

// ---------------- mma.sync / ldmatrix / cp.async helpers (sm_80+) ------
__device__ __forceinline__ uint32_t smem_u32(const void* p) {
    uint32_t a;
    asm("{ .reg .u64 tmp; cvta.to.shared.u64 tmp, %1; cvt.u32.u64 %0, tmp; }"
        : "=r"(a) : "l"(p));
    return a;
}
#define LDSM_X4(r0, r1, r2, r3, addr) \
    asm volatile("ldmatrix.sync.aligned.m8n8.x4.shared.b16 {%0,%1,%2,%3}, [%4];" \
        : "=r"(r0), "=r"(r1), "=r"(r2), "=r"(r3) : "r"(addr))

#define CPA16(dst, src) \
    asm volatile("cp.async.cg.shared.global [%0], [%1], 16;" :: "r"(dst), "l"(src))
#define CPA_COMMIT() asm volatile("cp.async.commit_group;")
#define CPA_WAIT1()  asm volatile("cp.async.wait_group 1;")
#define CPA_WAIT0()  asm volatile("cp.async.wait_group 0;")

__device__ __forceinline__ void mma_bf16(float c[4], const uint32_t a[4], const uint32_t b[2]) {
    asm volatile("mma.sync.aligned.m16n8k16.row.col.f32.bf16.bf16.f32 "
        "{%0,%1,%2,%3}, {%4,%5,%6,%7}, {%8,%9}, {%0,%1,%2,%3};"
        : "+f"(c[0]), "+f"(c[1]), "+f"(c[2]), "+f"(c[3])
        : "r"(a[0]), "r"(a[1]), "r"(a[2]), "r"(a[3]), "r"(b[0]), "r"(b[1]));
}

__device__ __forceinline__ void cvt_pair(float a, float b, uint32_t& hi2, uint32_t& lo2) {
    uint32_t ua = __float_as_uint(a), ub = __float_as_uint(b);
    hi2 = __byte_perm(ua, ub, 0x7632);
    float ra = a - __uint_as_float(ua & 0xffff0000u);
    float rb = b - __uint_as_float(ub & 0xffff0000u);
    asm("cvt.rn.bf16x2.f32 %0, %1, %2;" : "=r"(lo2) : "f"(rb), "f"(ra));
}

// ---------------- scratch ----------------
__device__ uint16_t g_Wqh0[INNER * DIM],  g_Wql0[INNER * DIM];
__device__ uint16_t g_Wqh1[INNER * DIM],  g_Wql1[INNER * DIM];
__device__ uint16_t g_Wkvh0[2 * INNER * DIM * 16], g_Wkvl0[2 * INNER * DIM * 16];
__device__ uint16_t g_Wkvh1[2 * INNER * DIM * 16], g_Wkvl1[2 * INNER * DIM * 16];
__device__ uint16_t g_Wouth0[DIM * INNER], g_Woutl0[DIM * INNER];
__device__ uint16_t g_Wouth1[DIM * INNER], g_Woutl1[DIM * INNER];
__device__ uint16_t g_Xh0[NB * DIM * YD], g_Xl0[NB * DIM * YD];
__device__ uint16_t g_Xh1[NB * DIM * YD], g_Xl1[NB * DIM * YD];
__device__ uint16_t g_Xth0[NB * DIM * YD], g_Xtl0[NB * DIM * YD];
__device__ uint16_t g_Xth1[NB * DIM * YD], g_Xtl1[NB * DIM * YD];
__device__ uint16_t g_Qth0[(size_t)NB * YD * INNER], g_Qtl0[(size_t)NB * YD * INNER];
__device__ uint16_t g_Qth1[(size_t)NB * YD * INNER], g_Qtl1[(size_t)NB * YD * INNER];
__device__ uint16_t g_Kth0[NB * HH * WW * 64], g_Ktl0[NB * HH * WW * 64];
__device__ uint16_t g_Kth1[NB * HH * WW * 64], g_Ktl1[NB * HH * WW * 64];
__device__ uint16_t g_Vh0[NB * INNER * WW], g_Vl0[NB * INNER * WW];
__device__ uint16_t g_Vh1[NB * INNER * WW], g_Vl1[NB * INNER * WW];
__device__ uint16_t g_Oh0[(size_t)NB * YD * INNER], g_Ol0[(size_t)NB * YD * INNER];
__device__ uint16_t g_Oh1[(size_t)NB * YD * INNER], g_Ol1[(size_t)NB * YD * INNER];

// =====================================================================
// Merged conversion kernel (unchanged from round 14)
// =====================================================================
__global__ __launch_bounds__(256) void cvt_all(
    const float* __restrict__ Wq0, uint16_t* __restrict__ Wqh0, uint16_t* __restrict__ Wql0,
    const float* __restrict__ Wq1, uint16_t* __restrict__ Wqh1, uint16_t* __restrict__ Wql1,
    const float* __restrict__ Wkv0, uint16_t* __restrict__ Wkvh0, uint16_t* __restrict__ Wkvl0,
    const float* __restrict__ Wkv1, uint16_t* __restrict__ Wkvh1, uint16_t* __restrict__ Wkvl1,
    const float* __restrict__ Wout0, uint16_t* __restrict__ Wouth0, uint16_t* __restrict__ Woutl0,
    const float* __restrict__ Wout1, uint16_t* __restrict__ Wouth1, uint16_t* __restrict__ Woutl1,
    const float* __restrict__ x0, uint16_t* __restrict__ Xh0, uint16_t* __restrict__ Xl0,
    uint16_t* __restrict__ Xth0, uint16_t* __restrict__ Xtl0,
    const float* __restrict__ x1, uint16_t* __restrict__ Xh1, uint16_t* __restrict__ Xl1,
    uint16_t* __restrict__ Xth1, uint16_t* __restrict__ Xtl1)
{
    __shared__ float tile[32][33];
    const int bid = blockIdx.x;
    const int t = threadIdx.x;

    if (bid < 8704) {
        const float* src; uint16_t *hi, *lo; int off;
        if (bid < 4096)      { src = Wkv0;  hi = Wkvh0;  lo = Wkvl0;  off = bid; }
        else if (bid < 8192) { src = Wkv1;  hi = Wkvh1;  lo = Wkvl1;  off = bid - 4096; }
        else if (bid < 8320) { src = Wq0;   hi = Wqh0;   lo = Wql0;   off = bid - 8192; }
        else if (bid < 8448) { src = Wq1;   hi = Wqh1;   lo = Wql1;   off = bid - 8320; }
        else if (bid < 8576) { src = Wout0; hi = Wouth0; lo = Woutl0; off = bid - 8448; }
        else                 { src = Wout1; hi = Wouth1; lo = Woutl1; off = bid - 8576; }
        size_t i = ((size_t)off * 256 + t) * 4;
        float4 f = *(const float4*)&src[i];
        uint32_t h0, l0, h1, l1;
        cvt_pair(f.x, f.y, h0, l0); cvt_pair(f.z, f.w, h1, l1);
        *(uint2*)&hi[i] = make_uint2(h0, h1);
        *(uint2*)&lo[i] = make_uint2(l0, l1);
        return;
    }

    const int xb = bid - 8704;
    const int z = xb >> 10, b = z & 7;
    const int rest = xb & 1023;
    const int n0 = (rest >> 7) * 32, y0 = (rest & 127) * 32;
    const float* x = (z < 8) ? x0 : x1;
    uint16_t* Xh  = (z < 8) ? Xh0  : Xh1;
    uint16_t* Xl  = (z < 8) ? Xl0  : Xl1;
    uint16_t* Xth = (z < 8) ? Xth0 : Xth1;
    uint16_t* Xtl = (z < 8) ? Xtl0 : Xtl1;
    const int r = t >> 3, c4 = (t & 7) * 4;

    float4 f = *(const float4*)&x[((size_t)b * DIM + n0 + r) * YD + y0 + c4];
    uint32_t h0, l0, h1, l1;
    cvt_pair(f.x, f.y, h0, l0); cvt_pair(f.z, f.w, h1, l1);
    size_t nat = ((size_t)b * DIM + n0 + r) * YD + y0 + c4;
    *(uint2*)&Xh[nat] = make_uint2(h0, h1);
    *(uint2*)&Xl[nat] = make_uint2(l0, l1);
    tile[r][c4 + 0] = f.x; tile[r][c4 + 1] = f.y;
    tile[r][c4 + 2] = f.z; tile[r][c4 + 3] = f.w;
    __syncthreads();
    float a0 = tile[c4 + 0][r], a1 = tile[c4 + 1][r];
    float a2 = tile[c4 + 2][r], a3 = tile[c4 + 3][r];
    cvt_pair(a0, a1, h0, l0); cvt_pair(a2, a3, h1, l1);
    size_t tr = ((size_t)b * YD + y0 + r) * DIM + n0 + c4;
    *(uint2*)&Xth[tr] = make_uint2(h0, h1);
    *(uint2*)&Xtl[tr] = make_uint2(l0, l1);
}

// =====================================================================
// GEMM core v2: 128-thread CTAs, 4 warps of 64x64, CTA tile 128x128,
// XOR-swizzled 64B rows, 3-stage cp.async, single barrier per chunk.
// =====================================================================
#define ARR   8192
#define STG   (4 * ARR)
#define GEMM_DSMEM (3 * STG)  // 98304 B

// copy one 64B row into one array: p01 -> c16{0,1}, p23 -> c16{2,3}
__device__ __forceinline__ void cpa_arr4(uint32_t r64, int s,
    const char* p01, const char* p23)
{
    CPA16(r64 + (uint32_t)((0 ^ s) << 4), p01);
    CPA16(r64 + (uint32_t)((1 ^ s) << 4), p01 + 16);
    CPA16(r64 + (uint32_t)((2 ^ s) << 4), p23);
    CPA16(r64 + (uint32_t)((3 ^ s) << 4), p23 + 16);
}

__device__ __forceinline__ void mma_chunk64(
    uint32_t base, float acc[4][8][4], int lane, int wm, int wn)
{
    const uint32_t aHi = base, aLo = base + ARR;
    const uint32_t bHi = base + 2 * ARR, bLo = base + 3 * ARR;
    const int arow  = lane & 15;
    const int acol8 = (lane >> 4) * 8;
    const int brow  = ((lane >> 4) & 1) * 8 + (lane & 7);
    const int bcol8 = ((lane >> 3) & 1) * 8;
    const int sA = (arow >> 1) & 3;
    const int sB = (brow >> 1) & 3;
#pragma unroll
    for (int ks = 0; ks < 32; ks += 16) {
        const uint32_t axu = (uint32_t)(((((ks + acol8) >> 3)) ^ sA) << 4);
        const uint32_t bxu = (uint32_t)(((((ks + bcol8) >> 3)) ^ sB) << 4);
        uint32_t bh[8][2], bl[8][2];
#pragma unroll
        for (int np = 0; np < 4; np++) {
            uint32_t off = (uint32_t)(wn + np * 16 + brow) * 64 + bxu;
            LDSM_X4(bh[np*2][0], bh[np*2][1], bh[np*2+1][0], bh[np*2+1][1], bHi + off);
            LDSM_X4(bl[np*2][0], bl[np*2][1], bl[np*2+1][0], bl[np*2+1][1], bLo + off);
        }
#pragma unroll
        for (int mt = 0; mt < 4; mt++) {
            uint32_t ah[4], al[4];
            uint32_t off = (uint32_t)(wm + mt * 16 + arow) * 64 + axu;
            LDSM_X4(ah[0], ah[1], ah[2], ah[3], aHi + off);
            LDSM_X4(al[0], al[1], al[2], al[3], aLo + off);
#pragma unroll
            for (int nt = 0; nt < 8; nt++) mma_bf16(acc[mt][nt], ah, bh[nt]);
#pragma unroll
            for (int nt = 0; nt < 8; nt++) mma_bf16(acc[mt][nt], ah, bl[nt]);
#pragma unroll
            for (int nt = 0; nt < 8; nt++) mma_bf16(acc[mt][nt], al, bh[nt]);
        }
    }
}

__device__ __forceinline__ void acc_to_tile64(
    float* tile, float acc[4][8][4], int lane, int wm, int wn)
{
    int g = lane >> 2, tt = lane & 3;
#pragma unroll
    for (int mt = 0; mt < 4; mt++) {
        int r = wm + mt * 16 + g;
#pragma unroll
        for (int nt = 0; nt < 8; nt++) {
            int cc = wn + nt * 8 + 2 * tt;
            tile[r * 129 + cc]           = acc[mt][nt][0];
            tile[r * 129 + cc + 1]       = acc[mt][nt][1];
            tile[(r + 8) * 129 + cc]     = acc[mt][nt][2];
            tile[(r + 8) * 129 + cc + 1] = acc[mt][nt][3];
        }
    }
}

// 3-stage loop; STAGE_M(c, stageaddr) issues copies + commit.
#define PIPE3(NC, STAGE_M) \
    STAGE_M(0, sbase); \
    STAGE_M(1, sbase + STG); \
    for (int c = 0; c < (NC); c++) { \
        if (c + 1 < (NC)) CPA_WAIT1(); else CPA_WAIT0(); \
        __syncthreads(); \
        if (c + 2 < (NC)) { STAGE_M(c + 2, sbase + ((c + 2) % 3) * STG); } \
        mma_chunk64(sbase + (c % 3) * STG, acc, lane, wm, wn); \
    }

#define GEMM_PROLOG \
    extern __shared__ char smg[]; \
    const uint32_t sbase = smem_u32(smg); \
    const int t = threadIdx.x, lane = t & 31, wid = t >> 5; \
    const int wm = (wid & 1) * 64, wn = (wid >> 1) * 64; \
    const int row = t; \
    const int sw = (row >> 1) & 3; \
    float acc[4][8][4]; \
    _Pragma("unroll") for (int i = 0; i < 4; i++) \
    _Pragma("unroll") for (int j = 0; j < 8; j++) \
    _Pragma("unroll") for (int q = 0; q < 4; q++) acc[i][j][q] = 0.f;

// =====================================================================
// Merged projection kernel: blocks [0,256) = kvproj, [256,2304) = qproj.
// 128 threads.
// =====================================================================
__global__ __launch_bounds__(128, 2) void proj_tc(
    const uint16_t* __restrict__ qAh0, const uint16_t* __restrict__ qAl0,
    const uint16_t* __restrict__ qBh0, const uint16_t* __restrict__ qBl0,
    uint16_t* __restrict__ Qh0g, uint16_t* __restrict__ Ql0g,
    const uint16_t* __restrict__ qAh1, const uint16_t* __restrict__ qAl1,
    const uint16_t* __restrict__ qBh1, const uint16_t* __restrict__ qBl1,
    uint16_t* __restrict__ Qh1g, uint16_t* __restrict__ Ql1g,
    const uint16_t* __restrict__ kAh0, const uint16_t* __restrict__ kAl0,
    const uint16_t* __restrict__ kBh0, const uint16_t* __restrict__ kBl0,
    uint16_t* __restrict__ Kh0g, uint16_t* __restrict__ Kl0g,
    uint16_t* __restrict__ Vh0g, uint16_t* __restrict__ Vl0g,
    const uint16_t* __restrict__ kAh1, const uint16_t* __restrict__ kAl1,
    const uint16_t* __restrict__ kBh1, const uint16_t* __restrict__ kBl1,
    uint16_t* __restrict__ Kh1g, uint16_t* __restrict__ Kl1g,
    uint16_t* __restrict__ Vh1g, uint16_t* __restrict__ Vl1g)
{
    GEMM_PROLOG
    const int bid = blockIdx.x;
    if (bid < 256) {
        // ---------------- kvproj: 128 chunks ----------------
        const int z = bid >> 4, b = z & 7;
        const int rest = bid & 15;
        const int m0 = (rest >> 1) * 128, w0 = (rest & 1) * 128;
        const int K = DIM * 16;
        const uint16_t* Ah = ((z < 8) ? kAh0 : kAh1) + (size_t)(m0 + row) * K;
        const uint16_t* Al = ((z < 8) ? kAl0 : kAl1) + (size_t)(m0 + row) * K;
        const size_t bOff = (size_t)b * DIM * YD + (size_t)(w0 + row) * 16;
        const uint16_t* Bh = ((z < 8) ? kBh0 : kBh1) + bOff;
        const uint16_t* Bl = ((z < 8) ? kBl0 : kBl1) + bOff;

#define STAGE_KV(cc, stg) do { \
        uint32_t r64 = (uint32_t)(stg) + (uint32_t)row * 64; \
        const char* pa  = (const char*)(Ah + (size_t)(cc) * 32); \
        const char* pal = (const char*)(Al + (size_t)(cc) * 32); \
        const char* pb  = (const char*)(Bh + (size_t)(2 * (cc)) * YD); \
        const char* pbl = (const char*)(Bl + (size_t)(2 * (cc)) * YD); \
        cpa_arr4(r64,           sw, pa,  pa + 32); \
        cpa_arr4(r64 + ARR,     sw, pal, pal + 32); \
        cpa_arr4(r64 + 2 * ARR, sw, pb,  pb + (size_t)YD * 2); \
        cpa_arr4(r64 + 3 * ARR, sw, pbl, pbl + (size_t)YD * 2); \
        CPA_COMMIT(); \
    } while (0)
        PIPE3(128, STAGE_KV)
#undef STAGE_KV

        if (m0 < 512) {
            uint16_t* Kh = (z < 8) ? Kh0g : Kh1g;
            uint16_t* Kl = (z < 8) ? Kl0g : Kl1g;
            float* tile = (float*)smg;
            __syncthreads();
            acc_to_tile64(tile, acc, lane, wm, wn);
            __syncthreads();
#pragma unroll
            for (int u = 0; u < 64; u++) {
                int p = u * 128 + t;
                int j = p >> 6, op = p & 63;
                int ol = 2 * op;
                float a = tile[ol * 129 + j];
                float c2 = tile[(ol + 1) * 129 + j];
                uint32_t hh, ll; cvt_pair(a, c2, hh, ll);
                int o = m0 + ol;
                int h = o >> 6, d = o & 63;
                size_t e = (((size_t)b * HH + h) * WW + w0 + j) * 64 + d;
                *(uint32_t*)&Kh[e] = hh;
                *(uint32_t*)&Kl[e] = ll;
            }
        } else {
            uint16_t* Vh = (z < 8) ? Vh0g : Vh1g;
            uint16_t* Vl = (z < 8) ? Vl0g : Vl1g;
            int g = lane >> 2, tt = lane & 3;
#pragma unroll
            for (int mt = 0; mt < 4; mt++) {
                int r = m0 + wm + mt * 16 + g;
#pragma unroll
                for (int nt = 0; nt < 8; nt++) {
                    int cc = w0 + wn + nt * 8 + 2 * tt;
                    uint32_t hh, ll;
                    cvt_pair(acc[mt][nt][0], acc[mt][nt][1], hh, ll);
                    size_t e = ((size_t)b * INNER + (r - 512)) * WW + cc;
                    *(uint32_t*)&Vh[e] = hh; *(uint32_t*)&Vl[e] = ll;
                    cvt_pair(acc[mt][nt][2], acc[mt][nt][3], hh, ll);
                    e = ((size_t)b * INNER + (r + 8 - 512)) * WW + cc;
                    *(uint32_t*)&Vh[e] = hh; *(uint32_t*)&Vl[e] = ll;
                }
            }
        }
    } else {
        // ---------------- qproj: 8 chunks ----------------
        const int qb = bid - 256;
        const int z = qb >> 7, b = z & 7;
        const int rest = qb & 127;
        const int m0 = (rest >> 5) * 128, n0 = (rest & 31) * 128;
        const uint16_t* Ah = ((z < 8) ? qAh0 : qAh1) + (size_t)(m0 + row) * DIM;
        const uint16_t* Al = ((z < 8) ? qAl0 : qAl1) + (size_t)(m0 + row) * DIM;
        const uint16_t* Bh = ((z < 8) ? qBh0 : qBh1) + ((size_t)b * YD + n0 + row) * DIM;
        const uint16_t* Bl = ((z < 8) ? qBl0 : qBl1) + ((size_t)b * YD + n0 + row) * DIM;
        uint16_t* Qh = (z < 8) ? Qh0g : Qh1g;
        uint16_t* Ql = (z < 8) ? Ql0g : Ql1g;

#define STAGE_Q(cc, stg) do { \
        uint32_t r64 = (uint32_t)(stg) + (uint32_t)row * 64; \
        const char* pa  = (const char*)(Ah + (cc) * 32); \
        const char* pal = (const char*)(Al + (cc) * 32); \
        const char* pb  = (const char*)(Bh + (cc) * 32); \
        const char* pbl = (const char*)(Bl + (cc) * 32); \
        cpa_arr4(r64,           sw, pa,  pa + 32); \
        cpa_arr4(r64 + ARR,     sw, pal, pal + 32); \
        cpa_arr4(r64 + 2 * ARR, sw, pb,  pb + 32); \
        cpa_arr4(r64 + 3 * ARR, sw, pbl, pbl + 32); \
        CPA_COMMIT(); \
    } while (0)
        PIPE3(8, STAGE_Q)
#undef STAGE_Q

        float* tile = (float*)smg;
        __syncthreads();
        acc_to_tile64(tile, acc, lane, wm, wn);
        __syncthreads();
#pragma unroll
        for (int u = 0; u < 64; u++) {
            int p = u * 128 + t;
            int y = p >> 6, op = p & 63;
            float a = tile[(2 * op) * 129 + y];
            float c2 = tile[(2 * op + 1) * 129 + y];
            uint32_t hh, ll; cvt_pair(a, c2, hh, ll);
            size_t e = ((size_t)b * YD + n0 + y) * INNER + m0 + 2 * op;
            *(uint32_t*)&Qh[e] = hh;
            *(uint32_t*)&Ql[e] = ll;
        }
    }
}

// =====================================================================
// Out projection (NT, both phases) + residual fuse. grid(32,2,8), 128 thr.
// =====================================================================
__global__ __launch_bounds__(128, 2) void outproj_tc(
    const uint16_t* __restrict__ Wh0, const uint16_t* __restrict__ Wl0,
    const uint16_t* __restrict__ Oh0, const uint16_t* __restrict__ Ol0,
    const uint16_t* __restrict__ Wh1, const uint16_t* __restrict__ Wl1,
    const uint16_t* __restrict__ Oh1, const uint16_t* __restrict__ Ol1,
    const float* __restrict__ b0, const float* __restrict__ b1,
    const float* __restrict__ x0, const float* __restrict__ x1,
    float* __restrict__ out)
{
    GEMM_PROLOG
    const int b = blockIdx.z;
    const int m0 = blockIdx.y * 128, n0 = blockIdx.x * 128;

    const size_t aOff = (size_t)(m0 + row) * INNER;
    const size_t bOff = ((size_t)b * YD + n0 + row) * INNER;
    const uint16_t* AH[2] = { Wh0 + aOff, Wh1 + aOff };
    const uint16_t* AL[2] = { Wl0 + aOff, Wl1 + aOff };
    const uint16_t* BH[2] = { Oh0 + bOff, Oh1 + bOff };
    const uint16_t* BL[2] = { Ol0 + bOff, Ol1 + bOff };

#define STAGE_O(cc, stg) do { \
    int phs = (cc) >> 4, k0 = ((cc) & 15) * 32; \
    uint32_t r64 = (uint32_t)(stg) + (uint32_t)row * 64; \
    const char* pa  = (const char*)(AH[phs] + k0); \
    const char* pal = (const char*)(AL[phs] + k0); \
    const char* pb  = (const char*)(BH[phs] + k0); \
    const char* pbl = (const char*)(BL[phs] + k0); \
    cpa_arr4(r64,           sw, pa,  pa + 32); \
    cpa_arr4(r64 + ARR,     sw, pal, pal + 32); \
    cpa_arr4(r64 + 2 * ARR, sw, pb,  pb + 32); \
    cpa_arr4(r64 + 3 * ARR, sw, pbl, pbl + 32); \
    CPA_COMMIT(); \
} while (0)
    PIPE3(32, STAGE_O)
#undef STAGE_O

    const int g = lane >> 2, tt = lane & 3;
#pragma unroll
    for (int mt = 0; mt < 4; mt++) {
        int r = m0 + wm + mt * 16 + g;
        float biasA = 0.5f * (b0[r] + b1[r]);
        float biasB = 0.5f * (b0[r + 8] + b1[r + 8]);
#pragma unroll
        for (int nt = 0; nt < 8; nt++) {
            int cc = n0 + wn + nt * 8 + 2 * tt;
            size_t iA = ((size_t)b * DIM + r) * YD + cc;
            size_t iB = ((size_t)b * DIM + r + 8) * YD + cc;
            float2 xa = *(const float2*)&x0[iA], xb = *(const float2*)&x1[iA];
            float2 oo;
            oo.x = 0.5f * (acc[mt][nt][0] + xa.x + xb.x) + biasA;
            oo.y = 0.5f * (acc[mt][nt][1] + xa.y + xb.y) + biasA;
            *(float2*)&out[iA] = oo;
            xa = *(const float2*)&x0[iB]; xb = *(const float2*)&x1[iB];
            oo.x = 0.5f * (acc[mt][nt][2] + xa.x + xb.x) + biasB;
            oo.y = 0.5f * (acc[mt][nt][3] + xa.y + xb.y) + biasB;
            *(float2*)&out[iB] = oo;
        }
    }
}

// =====================================================================
// Attention (unchanged round-14 form)
// =====================================================================
#define ATTN_DSMEM 98304
#define ASTAGE 32768
#define SWZ8(row, c16) (((uint32_t)(row)) * 128 + ((((uint32_t)(c16)) ^ ((row) & 7)) << 4))

__global__ __launch_bounds__(256, 2) void attn_tc(
    const uint16_t* __restrict__ Qh0, const uint16_t* __restrict__ Ql0,
    const uint16_t* __restrict__ Kha, const uint16_t* __restrict__ Kla,
    const uint16_t* __restrict__ Vha, const uint16_t* __restrict__ Vla,
    uint16_t* __restrict__ Oh0, uint16_t* __restrict__ Ol0,
    const uint16_t* __restrict__ Qh1, const uint16_t* __restrict__ Ql1,
    const uint16_t* __restrict__ Khb, const uint16_t* __restrict__ Klb,
    const uint16_t* __restrict__ Vhb, const uint16_t* __restrict__ Vlb,
    uint16_t* __restrict__ Oh1, uint16_t* __restrict__ Ol1)
{
    extern __shared__ char sm[];
    const uint32_t sb = smem_u32(sm);
    const int z = blockIdx.z, b = z & 7;
    const uint16_t* Qh = (z < NB) ? Qh0 : Qh1;
    const uint16_t* Ql = (z < NB) ? Ql0 : Ql1;
    const uint16_t* Kh = (z < NB) ? Kha : Khb;
    const uint16_t* Kl = (z < NB) ? Kla : Klb;
    const uint16_t* Vh = (z < NB) ? Vha : Vhb;
    const uint16_t* Vl = (z < NB) ? Vla : Vlb;
    uint16_t* Oh = (z < NB) ? Oh0 : Oh1;
    uint16_t* Ol = (z < NB) ? Ol0 : Ol1;
    const int h  = blockIdx.y;
    const int i0 = blockIdx.x * 128;

    const uint32_t uQh = sb, uQl = sb + 16384;
    const int t = threadIdx.x, lane = t & 31, wid = t >> 5;

    {
        int qr = t >> 1, qh2 = t & 1;
        const char* sh = (const char*)(Qh + ((size_t)(b * YD + i0 + qr)) * INNER + h * 64 + qh2 * 32);
        const char* sl = (const char*)(Ql + ((size_t)(b * YD + i0 + qr)) * INNER + h * 64 + qh2 * 32);
#pragma unroll
        for (int k = 0; k < 4; k++) {
            int c16 = qh2 * 4 + k;
            CPA16(uQh + SWZ8(qr, c16), sh + k * 16);
            CPA16(uQl + SWZ8(qr, c16), sl + k * 16);
        }
    }
    const int crow = t >> 2, cq = t & 3;
    const size_t kbase = (((size_t)b * HH + h) * WW) * 64 + (size_t)crow * 64 + cq * 16;
    const size_t vbase = ((size_t)b * INNER + h * 64 + crow) * WW + cq * 16;
#define STAGE_CHUNK(cc_) do { \
    uint32_t stg = sb + 32768 + ((cc_) & 1) * ASTAGE; \
    const char* ksh = (const char*)(Kh + kbase + (size_t)(cc_) * 64 * 64); \
    const char* ksl = (const char*)(Kl + kbase + (size_t)(cc_) * 64 * 64); \
    const char* vsh = (const char*)(Vh + vbase + (cc_) * 64); \
    const char* vsl = (const char*)(Vl + vbase + (cc_) * 64); \
    _Pragma("unroll") \
    for (int k = 0; k < 2; k++) { \
        int c16 = cq * 2 + k; \
        uint32_t sw2 = SWZ8(crow, c16); \
        CPA16(stg + sw2,         ksh + k * 16); \
        CPA16(stg + 8192 + sw2,  ksl + k * 16); \
        CPA16(stg + 16384 + sw2, vsh + k * 16); \
        CPA16(stg + 24576 + sw2, vsl + k * 16); \
    } \
} while (0)

    STAGE_CHUNK(0);
    CPA_COMMIT();

    const int arow  = lane & 15, acol8 = (lane >> 4) * 8;
    const int brow  = ((lane >> 4) & 1) * 8 + (lane & 7);
    const int bcol8 = ((lane >> 3) & 1) * 8;

    float m1 = -1e30f, m2 = -1e30f, sum1 = 0.f, sum2 = 0.f;
    float o[8][4];
#pragma unroll
    for (int dt = 0; dt < 8; dt++)
#pragma unroll
        for (int q = 0; q < 4; q++) o[dt][q] = 0.f;

    for (int c = 0; c < 4; c++) {
        CPA_WAIT0();
        __syncthreads();
        if (c + 1 < 4) { STAGE_CHUNK(c + 1); CPA_COMMIT(); }

        const uint32_t stg = sb + 32768 + (c & 1) * ASTAGE;
        const uint32_t uKh2 = stg, uKl2 = stg + 8192;
        const uint32_t uVh2 = stg + 16384, uVl2 = stg + 24576;

        float s[8][4];
#pragma unroll
        for (int nt = 0; nt < 8; nt++)
#pragma unroll
            for (int q = 0; q < 4; q++) s[nt][q] = 0.f;

#pragma unroll
        for (int kc = 0; kc < 4; kc++) {
            uint32_t ah[4], al[4];
            int ar = wid * 16 + arow;
            int ac16 = kc * 2 + (acol8 >> 3);
            uint32_t aoff = SWZ8(ar, ac16);
            LDSM_X4(ah[0], ah[1], ah[2], ah[3], uQh + aoff);
            LDSM_X4(al[0], al[1], al[2], al[3], uQl + aoff);
#pragma unroll
            for (int np = 0; np < 4; np++) {
                int br = np * 16 + brow;
                int bc16 = kc * 2 + (bcol8 >> 3);
                uint32_t boff = SWZ8(br, bc16);
                uint32_t bh[4], bl[4];
                LDSM_X4(bh[0], bh[1], bh[2], bh[3], uKh2 + boff);
                LDSM_X4(bl[0], bl[1], bl[2], bl[3], uKl2 + boff);
                mma_bf16(s[2*np],   ah, &bh[0]);
                mma_bf16(s[2*np+1], ah, &bh[2]);
                mma_bf16(s[2*np],   ah, &bl[0]);
                mma_bf16(s[2*np+1], ah, &bl[2]);
                mma_bf16(s[2*np],   al, &bh[0]);
                mma_bf16(s[2*np+1], al, &bh[2]);
            }
        }

        float cm1 = -1e30f, cm2 = -1e30f;
#pragma unroll
        for (int nt = 0; nt < 8; nt++) {
            s[nt][0] *= ASCALE; s[nt][1] *= ASCALE;
            s[nt][2] *= ASCALE; s[nt][3] *= ASCALE;
            cm1 = fmaxf(cm1, fmaxf(s[nt][0], s[nt][1]));
            cm2 = fmaxf(cm2, fmaxf(s[nt][2], s[nt][3]));
        }
        cm1 = fmaxf(cm1, __shfl_xor_sync(0xffffffffu, cm1, 1));
        cm1 = fmaxf(cm1, __shfl_xor_sync(0xffffffffu, cm1, 2));
        cm2 = fmaxf(cm2, __shfl_xor_sync(0xffffffffu, cm2, 1));
        cm2 = fmaxf(cm2, __shfl_xor_sync(0xffffffffu, cm2, 2));
        float m1n = fmaxf(m1, cm1), m2n = fmaxf(m2, cm2);
        float sc1 = __expf(m1 - m1n), sc2 = __expf(m2 - m2n);
        m1 = m1n; m2 = m2n;
#pragma unroll
        for (int dt = 0; dt < 8; dt++) {
            o[dt][0] *= sc1; o[dt][1] *= sc1;
            o[dt][2] *= sc2; o[dt][3] *= sc2;
        }
        float ls1 = 0.f, ls2 = 0.f;
#pragma unroll
        for (int nt = 0; nt < 8; nt++) {
            s[nt][0] = __expf(s[nt][0] - m1); ls1 += s[nt][0];
            s[nt][1] = __expf(s[nt][1] - m1); ls1 += s[nt][1];
            s[nt][2] = __expf(s[nt][2] - m2); ls2 += s[nt][2];
            s[nt][3] = __expf(s[nt][3] - m2); ls2 += s[nt][3];
        }
        sum1 = sum1 * sc1 + ls1;
        sum2 = sum2 * sc2 + ls2;

#pragma unroll
        for (int kk = 0; kk < 4; kk++) {
            uint32_t ph[4], pl[4];
            cvt_pair(s[2*kk][0],   s[2*kk][1],   ph[0], pl[0]);
            cvt_pair(s[2*kk][2],   s[2*kk][3],   ph[1], pl[1]);
            cvt_pair(s[2*kk+1][0], s[2*kk+1][1], ph[2], pl[2]);
            cvt_pair(s[2*kk+1][2], s[2*kk+1][3], ph[3], pl[3]);
#pragma unroll
            for (int dp = 0; dp < 4; dp++) {
                int vr = dp * 16 + brow;
                int vc16 = kk * 2 + (bcol8 >> 3);
                uint32_t voff = SWZ8(vr, vc16);
                uint32_t vh[4], vl[4];
                LDSM_X4(vh[0], vh[1], vh[2], vh[3], uVh2 + voff);
                LDSM_X4(vl[0], vl[1], vl[2], vl[3], uVl2 + voff);
                mma_bf16(o[2*dp],   ph, &vh[0]);
                mma_bf16(o[2*dp+1], ph, &vh[2]);
                mma_bf16(o[2*dp],   pl, &vh[0]);
                mma_bf16(o[2*dp+1], pl, &vh[2]);
                mma_bf16(o[2*dp],   ph, &vl[0]);
                mma_bf16(o[2*dp+1], ph, &vl[2]);
            }
        }
    }
#undef STAGE_CHUNK

    sum1 += __shfl_xor_sync(0xffffffffu, sum1, 1);
    sum1 += __shfl_xor_sync(0xffffffffu, sum1, 2);
    sum2 += __shfl_xor_sync(0xffffffffu, sum2, 1);
    sum2 += __shfl_xor_sync(0xffffffffu, sum2, 2);
    const float i1 = 1.f / sum1, i2 = 1.f / sum2;

    const int g = lane >> 2, tt = lane & 3;
    const int y = i0 + wid * 16 + g;
    size_t rb = ((size_t)b * YD + y) * INNER + h * 64;
#pragma unroll
    for (int dt = 0; dt < 8; dt++) {
        uint32_t hh, ll;
        size_t e = rb + dt * 8 + 2 * tt;
        cvt_pair(o[dt][0] * i1, o[dt][1] * i1, hh, ll);
        *(uint32_t*)&Oh[e] = hh;  *(uint32_t*)&Ol[e] = ll;
        e += (size_t)8 * INNER;
        cvt_pair(o[dt][2] * i2, o[dt][3] * i2, hh, ll);
        *(uint32_t*)&Oh[e] = hh;  *(uint32_t*)&Ol[e] = ll;
    }
}

// =====================================================================
extern "C" void kernel_launch(void* const* d_in, const int* in_sizes, int n_in,
                              void* d_out, int out_size)
{
    const float* x0    = (const float*)d_in[0];
    const float* x1    = (const float*)d_in[1];
    const float* Wq0   = (const float*)d_in[2];
    const float* Wkv0  = (const float*)d_in[3];
    const float* Wq1   = (const float*)d_in[4];
    const float* Wkv1  = (const float*)d_in[5];
    const float* Wout0 = (const float*)d_in[6];
    const float* bout0 = (const float*)d_in[7];
    const float* Wout1 = (const float*)d_in[8];
    const float* bout1 = (const float*)d_in[9];
    float* out = (float*)d_out;

    uint16_t *Wqh0, *Wql0, *Wqh1, *Wql1, *Wkvh0, *Wkvl0, *Wkvh1, *Wkvl1;
    uint16_t *Wouth0, *Woutl0, *Wouth1, *Woutl1;
    uint16_t *Xh0, *Xl0, *Xh1, *Xl1, *Xth0, *Xtl0, *Xth1, *Xtl1;
    uint16_t *Qth0, *Qtl0, *Qth1, *Qtl1;
    uint16_t *Kth0, *Ktl0, *Kth1, *Ktl1, *Vh0, *Vl0, *Vh1, *Vl1;
    uint16_t *Oh0, *Ol0, *Oh1, *Ol1;
    cudaGetSymbolAddress((void**)&Wqh0, g_Wqh0);   cudaGetSymbolAddress((void**)&Wql0, g_Wql0);
    cudaGetSymbolAddress((void**)&Wqh1, g_Wqh1);   cudaGetSymbolAddress((void**)&Wql1, g_Wql1);
    cudaGetSymbolAddress((void**)&Wkvh0, g_Wkvh0); cudaGetSymbolAddress((void**)&Wkvl0, g_Wkvl0);
    cudaGetSymbolAddress((void**)&Wkvh1, g_Wkvh1); cudaGetSymbolAddress((void**)&Wkvl1, g_Wkvl1);
    cudaGetSymbolAddress((void**)&Wouth0, g_Wouth0); cudaGetSymbolAddress((void**)&Woutl0, g_Woutl0);
    cudaGetSymbolAddress((void**)&Wouth1, g_Wouth1); cudaGetSymbolAddress((void**)&Woutl1, g_Woutl1);
    cudaGetSymbolAddress((void**)&Xh0, g_Xh0);   cudaGetSymbolAddress((void**)&Xl0, g_Xl0);
    cudaGetSymbolAddress((void**)&Xh1, g_Xh1);   cudaGetSymbolAddress((void**)&Xl1, g_Xl1);
    cudaGetSymbolAddress((void**)&Xth0, g_Xth0); cudaGetSymbolAddress((void**)&Xtl0, g_Xtl0);
    cudaGetSymbolAddress((void**)&Xth1, g_Xth1); cudaGetSymbolAddress((void**)&Xtl1, g_Xtl1);
    cudaGetSymbolAddress((void**)&Qth0, g_Qth0); cudaGetSymbolAddress((void**)&Qtl0, g_Qtl0);
    cudaGetSymbolAddress((void**)&Qth1, g_Qth1); cudaGetSymbolAddress((void**)&Qtl1, g_Qtl1);
    cudaGetSymbolAddress((void**)&Kth0, g_Kth0); cudaGetSymbolAddress((void**)&Ktl0, g_Ktl0);
    cudaGetSymbolAddress((void**)&Kth1, g_Kth1); cudaGetSymbolAddress((void**)&Ktl1, g_Ktl1);
    cudaGetSymbolAddress((void**)&Vh0, g_Vh0);   cudaGetSymbolAddress((void**)&Vl0, g_Vl0);
    cudaGetSymbolAddress((void**)&Vh1, g_Vh1);   cudaGetSymbolAddress((void**)&Vl1, g_Vl1);
    cudaGetSymbolAddress((void**)&Oh0, g_Oh0);   cudaGetSymbolAddress((void**)&Ol0, g_Ol0);
    cudaGetSymbolAddress((void**)&Oh1, g_Oh1);   cudaGetSymbolAddress((void**)&Ol1, g_Ol1);

    cudaFuncSetAttribute(proj_tc,    cudaFuncAttributeMaxDynamicSharedMemorySize, GEMM_DSMEM);
    cudaFuncSetAttribute(outproj_tc, cudaFuncAttributeMaxDynamicSharedMemorySize, GEMM_DSMEM);
    cudaFuncSetAttribute(attn_tc,    cudaFuncAttributeMaxDynamicSharedMemorySize, ATTN_DSMEM);

    cvt_all<<<dim3(8704 + 16384, 1, 1), 256>>>(
        Wq0, Wqh0, Wql0, Wq1, Wqh1, Wql1,
        Wkv0, Wkvh0, Wkvl0, Wkv1, Wkvh1, Wkvl1,
        Wout0, Wouth0, Woutl0, Wout1, Wouth1, Woutl1,
        x0, Xh0, Xl0, Xth0, Xtl0, x1, Xh1, Xl1, Xth1, Xtl1);

    proj_tc<<<dim3(2304, 1, 1), 128, GEMM_DSMEM>>>(
        Wqh0, Wql0, Xth0, Xtl0, Qth0, Qtl0,
        Wqh1, Wql1, Xth1, Xtl1, Qth1, Qtl1,
        Wkvh0, Wkvl0, Xh0, Xl0, Kth0, Ktl0, Vh0, Vl0,
        Wkvh1, Wkvl1, Xh1, Xl1, Kth1, Ktl1, Vh1, Vl1);
    attn_tc<<<dim3(YD / 128, HH, 2 * NB), 256, ATTN_DSMEM>>>(
        Qth0, Qtl0, Kth1, Ktl1, Vh1, Vl1, Oh0, Ol0,
        Qth1, Qtl1, Kth0, Ktl0, Vh0, Vl0, Oh1, Ol1);
    outproj_tc<<<dim3(YD / 128, DIM / 128, NB), 128, GEMM_DSMEM>>>(
        Wouth0, Woutl0, Oh0, Ol0, Wouth1, Woutl1, Oh1, Ol1,
        bout0, bout1, x0, x1, out);
}

// round 16
// speedup vs baseline: 1.2040x; 1.2040x over previous
#include <cuda_runtime.h>
#include <math.h>
#include <cstdint>

#define NB    8
#define DIM   256
#define YD    4096
#define HH    8
#define INNER 512
#define WW    256
#define ASCALE 0.125f

// ---------------- mma.sync / ldmatrix / cp.async helpers (sm_80+) ------
__device__ __forceinline__ uint32_t smem_u32(const void* p) {
    uint32_t a;
    asm("{ .reg .u64 tmp; cvta.to.shared.u64 tmp, %1; cvt.u32.u64 %0, tmp; }"
        : "=r"(a) : "l"(p));
    return a;
}
#define LDSM_X4(r0, r1, r2, r3, addr) \
    asm volatile("ldmatrix.sync.aligned.m8n8.x4.shared.b16 {%0,%1,%2,%3}, [%4];" \
        : "=r"(r0), "=r"(r1), "=r"(r2), "=r"(r3) : "r"(addr))

#define CPA16(dst, src) \
    asm volatile("cp.async.cg.shared.global [%0], [%1], 16;" :: "r"(dst), "l"(src))
#define CPA_COMMIT() asm volatile("cp.async.commit_group;")
#define CPA_WAIT1()  asm volatile("cp.async.wait_group 1;")
#define CPA_WAIT0()  asm volatile("cp.async.wait_group 0;")

__device__ __forceinline__ void mma_bf16(float c[4], const uint32_t a[4], const uint32_t b[2]) {
    asm volatile("mma.sync.aligned.m16n8k16.row.col.f32.bf16.bf16.f32 "
        "{%0,%1,%2,%3}, {%4,%5,%6,%7}, {%8,%9}, {%0,%1,%2,%3};"
        : "+f"(c[0]), "+f"(c[1]), "+f"(c[2]), "+f"(c[3])
        : "r"(a[0]), "r"(a[1]), "r"(a[2]), "r"(a[3]), "r"(b[0]), "r"(b[1]));
}

__device__ __forceinline__ void cvt_pair(float a, float b, uint32_t& hi2, uint32_t& lo2) {
    uint32_t ua = __float_as_uint(a), ub = __float_as_uint(b);
    hi2 = __byte_perm(ua, ub, 0x7632);
    float ra = a - __uint_as_float(ua & 0xffff0000u);
    float rb = b - __uint_as_float(ub & 0xffff0000u);
    asm("cvt.rn.bf16x2.f32 %0, %1, %2;" : "=r"(lo2) : "f"(rb), "f"(ra));
}

// ---------------- scratch ----------------
__device__ uint16_t g_Wqh0[INNER * DIM],  g_Wql0[INNER * DIM];
__device__ uint16_t g_Wqh1[INNER * DIM],  g_Wql1[INNER * DIM];
__device__ uint16_t g_Wkvh0[2 * INNER * DIM * 16], g_Wkvl0[2 * INNER * DIM * 16];
__device__ uint16_t g_Wkvh1[2 * INNER * DIM * 16], g_Wkvl1[2 * INNER * DIM * 16];
__device__ uint16_t g_Wouth0[DIM * INNER], g_Woutl0[DIM * INNER];
__device__ uint16_t g_Wouth1[DIM * INNER], g_Woutl1[DIM * INNER];
__device__ uint16_t g_Xh0[NB * DIM * YD], g_Xl0[NB * DIM * YD];
__device__ uint16_t g_Xh1[NB * DIM * YD], g_Xl1[NB * DIM * YD];
__device__ uint16_t g_Xth0[NB * DIM * YD], g_Xtl0[NB * DIM * YD];
__device__ uint16_t g_Xth1[NB * DIM * YD], g_Xtl1[NB * DIM * YD];
__device__ uint16_t g_Qth0[(size_t)NB * YD * INNER], g_Qtl0[(size_t)NB * YD * INNER];
__device__ uint16_t g_Qth1[(size_t)NB * YD * INNER], g_Qtl1[(size_t)NB * YD * INNER];
__device__ uint16_t g_Kth0[NB * HH * WW * 64], g_Ktl0[NB * HH * WW * 64];
__device__ uint16_t g_Kth1[NB * HH * WW * 64], g_Ktl1[NB * HH * WW * 64];
__device__ uint16_t g_Vh0[NB * INNER * WW], g_Vl0[NB * INNER * WW];
__device__ uint16_t g_Vh1[NB * INNER * WW], g_Vl1[NB * INNER * WW];
__device__ uint16_t g_Oh0[(size_t)NB * YD * INNER], g_Ol0[(size_t)NB * YD * INNER];
__device__ uint16_t g_Oh1[(size_t)NB * YD * INNER], g_Ol1[(size_t)NB * YD * INNER];

// =====================================================================
// Merged conversion kernel; transposed-X store now emits 16B uint4.
// blocks [0,8704): linear hi/lo cvt; [8704, 25088): x tile transpose+cvt.
// =====================================================================
__global__ __launch_bounds__(256) void cvt_all(
    const float* __restrict__ Wq0, uint16_t* __restrict__ Wqh0, uint16_t* __restrict__ Wql0,
    const float* __restrict__ Wq1, uint16_t* __restrict__ Wqh1, uint16_t* __restrict__ Wql1,
    const float* __restrict__ Wkv0, uint16_t* __restrict__ Wkvh0, uint16_t* __restrict__ Wkvl0,
    const float* __restrict__ Wkv1, uint16_t* __restrict__ Wkvh1, uint16_t* __restrict__ Wkvl1,
    const float* __restrict__ Wout0, uint16_t* __restrict__ Wouth0, uint16_t* __restrict__ Woutl0,
    const float* __restrict__ Wout1, uint16_t* __restrict__ Wouth1, uint16_t* __restrict__ Woutl1,
    const float* __restrict__ x0, uint16_t* __restrict__ Xh0, uint16_t* __restrict__ Xl0,
    uint16_t* __restrict__ Xth0, uint16_t* __restrict__ Xtl0,
    const float* __restrict__ x1, uint16_t* __restrict__ Xh1, uint16_t* __restrict__ Xl1,
    uint16_t* __restrict__ Xth1, uint16_t* __restrict__ Xtl1)
{
    __shared__ float tile[32][33];
    const int bid = blockIdx.x;
    const int t = threadIdx.x;

    if (bid < 8704) {
        const float* src; uint16_t *hi, *lo; int off;
        if (bid < 4096)      { src = Wkv0;  hi = Wkvh0;  lo = Wkvl0;  off = bid; }
        else if (bid < 8192) { src = Wkv1;  hi = Wkvh1;  lo = Wkvl1;  off = bid - 4096; }
        else if (bid < 8320) { src = Wq0;   hi = Wqh0;   lo = Wql0;   off = bid - 8192; }
        else if (bid < 8448) { src = Wq1;   hi = Wqh1;   lo = Wql1;   off = bid - 8320; }
        else if (bid < 8576) { src = Wout0; hi = Wouth0; lo = Woutl0; off = bid - 8448; }
        else                 { src = Wout1; hi = Wouth1; lo = Woutl1; off = bid - 8576; }
        size_t i = ((size_t)off * 256 + t) * 4;
        float4 f = *(const float4*)&src[i];
        uint32_t h0, l0, h1, l1;
        cvt_pair(f.x, f.y, h0, l0); cvt_pair(f.z, f.w, h1, l1);
        *(uint2*)&hi[i] = make_uint2(h0, h1);
        *(uint2*)&lo[i] = make_uint2(l0, l1);
        return;
    }

    const int xb = bid - 8704;
    const int z = xb >> 10, b = z & 7;
    const int rest = xb & 1023;
    const int n0 = (rest >> 7) * 32, y0 = (rest & 127) * 32;
    const float* x = (z < 8) ? x0 : x1;
    uint16_t* Xh  = (z < 8) ? Xh0  : Xh1;
    uint16_t* Xl  = (z < 8) ? Xl0  : Xl1;
    uint16_t* Xth = (z < 8) ? Xth0 : Xth1;
    uint16_t* Xtl = (z < 8) ? Xtl0 : Xtl1;
    const int r = t >> 3, c4 = (t & 7) * 4;

    float4 f = *(const float4*)&x[((size_t)b * DIM + n0 + r) * YD + y0 + c4];
    uint32_t h0, l0, h1, l1;
    cvt_pair(f.x, f.y, h0, l0); cvt_pair(f.z, f.w, h1, l1);
    size_t nat = ((size_t)b * DIM + n0 + r) * YD + y0 + c4;
    *(uint2*)&Xh[nat] = make_uint2(h0, h1);
    *(uint2*)&Xl[nat] = make_uint2(l0, l1);
    tile[r][c4 + 0] = f.x; tile[r][c4 + 1] = f.y;
    tile[r][c4 + 2] = f.z; tile[r][c4 + 3] = f.w;
    __syncthreads();
    // transpose phase: 128 threads, each owns 1 y-row x 8 n-cols -> 16B stores
    if (t < 128) {
        const int r2 = t >> 2, c8 = (t & 3) * 8;
        uint32_t hh[4], ll[4];
#pragma unroll
        for (int j = 0; j < 4; j++) {
            float a0 = tile[c8 + 2 * j][r2];
            float a1 = tile[c8 + 2 * j + 1][r2];
            cvt_pair(a0, a1, hh[j], ll[j]);
        }
        size_t tr = ((size_t)b * YD + y0 + r2) * DIM + n0 + c8;
        *(uint4*)&Xth[tr] = make_uint4(hh[0], hh[1], hh[2], hh[3]);
        *(uint4*)&Xtl[tr] = make_uint4(ll[0], ll[1], ll[2], ll[3]);
    }
}

// =====================================================================
// GEMM common: 128x32 bf16 tiles, XOR-swizzled 64B rows, 3-stage cp.async
// (round-14 proven config: 256 thr, 8 warps of 64x32, 2 CTAs/SM)
// =====================================================================
#define ARR   8192
#define STG   (4 * ARR)
#define GEMM_DSMEM (3 * STG)  // 98304 B

__device__ __forceinline__ void cpa_chunk(uint32_t stage, int row, int h,
    const uint16_t* __restrict__ sAh, const uint16_t* __restrict__ sAl,
    const uint16_t* __restrict__ sBh, const uint16_t* __restrict__ sBl)
{
    const int s = (row >> 1) & 3;
    const uint32_t r64 = stage + (uint32_t)row * 64;
    const uint32_t u0 = (uint32_t)(((2 * h)     ^ s) << 4);
    const uint32_t u1 = (uint32_t)(((2 * h + 1) ^ s) << 4);
    CPA16(r64 + u0,           (const char*)sAh);
    CPA16(r64 + u1,           (const char*)sAh + 16);
    CPA16(r64 + ARR + u0,     (const char*)sAl);
    CPA16(r64 + ARR + u1,     (const char*)sAl + 16);
    CPA16(r64 + 2 * ARR + u0, (const char*)sBh);
    CPA16(r64 + 2 * ARR + u1, (const char*)sBh + 16);
    CPA16(r64 + 3 * ARR + u0, (const char*)sBl);
    CPA16(r64 + 3 * ARR + u1, (const char*)sBl + 16);
}

__device__ __forceinline__ void mma_chunk3(
    uint32_t base, float acc[4][4][4], int lane, int wm, int wn)
{
    const uint32_t aHi = base, aLo = base + ARR;
    const uint32_t bHi = base + 2 * ARR, bLo = base + 3 * ARR;
    const int arow  = lane & 15;
    const int acol8 = (lane >> 4) * 8;
    const int brow  = ((lane >> 4) & 1) * 8 + (lane & 7);
    const int bcol8 = ((lane >> 3) & 1) * 8;
    const int sA = (arow >> 1) & 3;
    const int sB = (brow >> 1) & 3;
#pragma unroll
    for (int ks = 0; ks < 32; ks += 16) {
        const uint32_t axu = (uint32_t)(((((ks + acol8) >> 3)) ^ sA) << 4);
        const uint32_t bxu = (uint32_t)(((((ks + bcol8) >> 3)) ^ sB) << 4);
        uint32_t bh[4][2], bl[4][2];
#pragma unroll
        for (int np = 0; np < 2; np++) {
            uint32_t off = (uint32_t)(wn + np * 16 + brow) * 64 + bxu;
            LDSM_X4(bh[np*2][0], bh[np*2][1], bh[np*2+1][0], bh[np*2+1][1], bHi + off);
            LDSM_X4(bl[np*2][0], bl[np*2][1], bl[np*2+1][0], bl[np*2+1][1], bLo + off);
        }
#pragma unroll
        for (int mt = 0; mt < 4; mt++) {
            uint32_t ah[4], al[4];
            uint32_t off = (uint32_t)(wm + mt * 16 + arow) * 64 + axu;
            LDSM_X4(ah[0], ah[1], ah[2], ah[3], aHi + off);
            LDSM_X4(al[0], al[1], al[2], al[3], aLo + off);
#pragma unroll
            for (int nt = 0; nt < 4; nt++) mma_bf16(acc[mt][nt], ah, bh[nt]);
#pragma unroll
            for (int nt = 0; nt < 4; nt++) mma_bf16(acc[mt][nt], ah, bl[nt]);
#pragma unroll
            for (int nt = 0; nt < 4; nt++) mma_bf16(acc[mt][nt], al, bh[nt]);
        }
    }
}

__device__ __forceinline__ void acc_to_tile(
    float* tile, float acc[4][4][4], int lane, int wm, int wn)
{
    int g = lane >> 2, tt = lane & 3;
#pragma unroll
    for (int mt = 0; mt < 4; mt++) {
        int r = wm + mt * 16 + g;
#pragma unroll
        for (int nt = 0; nt < 4; nt++) {
            int cc = wn + nt * 8 + 2 * tt;
            tile[r * 129 + cc]           = acc[mt][nt][0];
            tile[r * 129 + cc + 1]       = acc[mt][nt][1];
            tile[(r + 8) * 129 + cc]     = acc[mt][nt][2];
            tile[(r + 8) * 129 + cc + 1] = acc[mt][nt][3];
        }
    }
}

#define PIPE_LOOP(NC, SRC_A_H, SRC_A_L, SRC_B_H, SRC_B_L) \
    cpa_chunk(sbase, row, half, SRC_A_H(0), SRC_A_L(0), SRC_B_H(0), SRC_B_L(0)); \
    CPA_COMMIT(); \
    cpa_chunk(sbase + STG, row, half, SRC_A_H(1), SRC_A_L(1), SRC_B_H(1), SRC_B_L(1)); \
    CPA_COMMIT(); \
    for (int c = 0; c < (NC); c++) { \
        if (c + 1 < (NC)) CPA_WAIT1(); else CPA_WAIT0(); \
        __syncthreads(); \
        if (c + 2 < (NC)) { \
            cpa_chunk(sbase + ((c + 2) % 3) * STG, row, half, \
                      SRC_A_H(c + 2), SRC_A_L(c + 2), SRC_B_H(c + 2), SRC_B_L(c + 2)); \
            CPA_COMMIT(); \
        } \
        mma_chunk3(sbase + (c % 3) * STG, acc, lane, wm, wn); \
    }

// =====================================================================
// Merged projection kernel: blocks [0,256) = kvproj, [256,2304) = qproj.
// =====================================================================
__global__ __launch_bounds__(256, 2) void proj_tc(
    const uint16_t* __restrict__ qAh0, const uint16_t* __restrict__ qAl0,
    const uint16_t* __restrict__ qBh0, const uint16_t* __restrict__ qBl0,
    uint16_t* __restrict__ Qh0g, uint16_t* __restrict__ Ql0g,
    const uint16_t* __restrict__ qAh1, const uint16_t* __restrict__ qAl1,
    const uint16_t* __restrict__ qBh1, const uint16_t* __restrict__ qBl1,
    uint16_t* __restrict__ Qh1g, uint16_t* __restrict__ Ql1g,
    const uint16_t* __restrict__ kAh0, const uint16_t* __restrict__ kAl0,
    const uint16_t* __restrict__ kBh0, const uint16_t* __restrict__ kBl0,
    uint16_t* __restrict__ Kh0g, uint16_t* __restrict__ Kl0g,
    uint16_t* __restrict__ Vh0g, uint16_t* __restrict__ Vl0g,
    const uint16_t* __restrict__ kAh1, const uint16_t* __restrict__ kAl1,
    const uint16_t* __restrict__ kBh1, const uint16_t* __restrict__ kBl1,
    uint16_t* __restrict__ Kh1g, uint16_t* __restrict__ Kl1g,
    uint16_t* __restrict__ Vh1g, uint16_t* __restrict__ Vl1g)
{
    extern __shared__ char smg[];
    const uint32_t sbase = smem_u32(smg);
    const int t = threadIdx.x, lane = t & 31, wid = t >> 5;
    const int wm = (wid & 1) * 64, wn = (wid >> 1) * 32;
    const int row = t >> 1, half = t & 1;
    float acc[4][4][4];
#pragma unroll
    for (int i = 0; i < 4; i++)
#pragma unroll
        for (int j = 0; j < 4; j++)
#pragma unroll
            for (int q = 0; q < 4; q++) acc[i][j][q] = 0.f;

    const int bid = blockIdx.x;
    if (bid < 256) {
        const int z = bid >> 4, b = z & 7;
        const int rest = bid & 15;
        const int m0 = (rest >> 1) * 128, w0 = (rest & 1) * 128;
        const int K = DIM * 16;
        const uint16_t* Ah = ((z < 8) ? kAh0 : kAh1) + (size_t)(m0 + row) * K + half * 16;
        const uint16_t* Al = ((z < 8) ? kAl0 : kAl1) + (size_t)(m0 + row) * K + half * 16;
        const size_t bOff = (size_t)b * DIM * YD + (size_t)half * YD + (size_t)(w0 + row) * 16;
        const uint16_t* Bh = ((z < 8) ? kBh0 : kBh1) + bOff;
        const uint16_t* Bl = ((z < 8) ? kBl0 : kBl1) + bOff;

#define KA_H(c) (Ah + (size_t)(c) * 32)
#define KA_L(c) (Al + (size_t)(c) * 32)
#define KB_H(c) (Bh + (size_t)(2 * (c)) * YD)
#define KB_L(c) (Bl + (size_t)(2 * (c)) * YD)
        PIPE_LOOP(128, KA_H, KA_L, KB_H, KB_L)
#undef KA_H
#undef KA_L
#undef KB_H
#undef KB_L

        if (m0 < 512) {
            uint16_t* Kh = (z < 8) ? Kh0g : Kh1g;
            uint16_t* Kl = (z < 8) ? Kl0g : Kl1g;
            float* tile = (float*)smg;
            __syncthreads();
            acc_to_tile(tile, acc, lane, wm, wn);
            __syncthreads();
#pragma unroll
            for (int u = 0; u < 32; u++) {
                int p = u * 256 + t;
                int j = p >> 6, op = p & 63;
                int ol = 2 * op;
                float a = tile[ol * 129 + j];
                float c2 = tile[(ol + 1) * 129 + j];
                uint32_t hh, ll; cvt_pair(a, c2, hh, ll);
                int o = m0 + ol;
                int h = o >> 6, d = o & 63;
                size_t e = (((size_t)b * HH + h) * WW + w0 + j) * 64 + d;
                *(uint32_t*)&Kh[e] = hh;
                *(uint32_t*)&Kl[e] = ll;
            }
        } else {
            uint16_t* Vh = (z < 8) ? Vh0g : Vh1g;
            uint16_t* Vl = (z < 8) ? Vl0g : Vl1g;
            int g = lane >> 2, tt = lane & 3;
#pragma unroll
            for (int mt = 0; mt < 4; mt++) {
                int r = m0 + wm + mt * 16 + g;
#pragma unroll
                for (int nt = 0; nt < 4; nt++) {
                    int cc = w0 + wn + nt * 8 + 2 * tt;
                    uint32_t hh, ll;
                    cvt_pair(acc[mt][nt][0], acc[mt][nt][1], hh, ll);
                    size_t e = ((size_t)b * INNER + (r - 512)) * WW + cc;
                    *(uint32_t*)&Vh[e] = hh; *(uint32_t*)&Vl[e] = ll;
                    cvt_pair(acc[mt][nt][2], acc[mt][nt][3], hh, ll);
                    e = ((size_t)b * INNER + (r + 8 - 512)) * WW + cc;
                    *(uint32_t*)&Vh[e] = hh; *(uint32_t*)&Vl[e] = ll;
                }
            }
        }
    } else {
        const int qb = bid - 256;
        const int z = qb >> 7, b = z & 7;
        const int rest = qb & 127;
        const int m0 = (rest >> 5) * 128, n0 = (rest & 31) * 128;
        const uint16_t* Ah = ((z < 8) ? qAh0 : qAh1) + (size_t)(m0 + row) * DIM + half * 16;
        const uint16_t* Al = ((z < 8) ? qAl0 : qAl1) + (size_t)(m0 + row) * DIM + half * 16;
        const uint16_t* Bh = ((z < 8) ? qBh0 : qBh1) + ((size_t)b * YD + n0 + row) * DIM + half * 16;
        const uint16_t* Bl = ((z < 8) ? qBl0 : qBl1) + ((size_t)b * YD + n0 + row) * DIM + half * 16;
        uint16_t* Qh = (z < 8) ? Qh0g : Qh1g;
        uint16_t* Ql = (z < 8) ? Ql0g : Ql1g;

#define QA_H(c) (Ah + (c) * 32)
#define QA_L(c) (Al + (c) * 32)
#define QB_H(c) (Bh + (c) * 32)
#define QB_L(c) (Bl + (c) * 32)
        PIPE_LOOP(8, QA_H, QA_L, QB_H, QB_L)
#undef QA_H
#undef QA_L
#undef QB_H
#undef QB_L

        float* tile = (float*)smg;
        __syncthreads();
        acc_to_tile(tile, acc, lane, wm, wn);
        __syncthreads();
#pragma unroll
        for (int u = 0; u < 32; u++) {
            int p = u * 256 + t;
            int y = p >> 6, op = p & 63;
            float a = tile[(2 * op) * 129 + y];
            float c2 = tile[(2 * op + 1) * 129 + y];
            uint32_t hh, ll; cvt_pair(a, c2, hh, ll);
            size_t e = ((size_t)b * YD + n0 + y) * INNER + m0 + 2 * op;
            *(uint32_t*)&Qh[e] = hh;
            *(uint32_t*)&Ql[e] = ll;
        }
    }
}

// =====================================================================
// Attention: cp.async staging, double-buffered K/V chunks, online softmax.
// =====================================================================
#define ATTN_DSMEM 98304
#define ASTAGE 32768
#define SWZ8(row, c16) (((uint32_t)(row)) * 128 + ((((uint32_t)(c16)) ^ ((row) & 7)) << 4))

__global__ __launch_bounds__(256, 2) void attn_tc(
    const uint16_t* __restrict__ Qh0, const uint16_t* __restrict__ Ql0,
    const uint16_t* __restrict__ Kha, const uint16_t* __restrict__ Kla,
    const uint16_t* __restrict__ Vha, const uint16_t* __restrict__ Vla,
    uint16_t* __restrict__ Oh0, uint16_t* __restrict__ Ol0,
    const uint16_t* __restrict__ Qh1, const uint16_t* __restrict__ Ql1,
    const uint16_t* __restrict__ Khb, const uint16_t* __restrict__ Klb,
    const uint16_t* __restrict__ Vhb, const uint16_t* __restrict__ Vlb,
    uint16_t* __restrict__ Oh1, uint16_t* __restrict__ Ol1)
{
    extern __shared__ char sm[];
    const uint32_t sb = smem_u32(sm);
    const int z = blockIdx.z, b = z & 7;
    const uint16_t* Qh = (z < NB) ? Qh0 : Qh1;
    const uint16_t* Ql = (z < NB) ? Ql0 : Ql1;
    const uint16_t* Kh = (z < NB) ? Kha : Khb;
    const uint16_t* Kl = (z < NB) ? Kla : Klb;
    const uint16_t* Vh = (z < NB) ? Vha : Vhb;
    const uint16_t* Vl = (z < NB) ? Vla : Vlb;
    uint16_t* Oh = (z < NB) ? Oh0 : Oh1;
    uint16_t* Ol = (z < NB) ? Ol0 : Ol1;
    const int h  = blockIdx.y;
    const int i0 = blockIdx.x * 128;

    const uint32_t uQh = sb, uQl = sb + 16384;
    const int t = threadIdx.x, lane = t & 31, wid = t >> 5;

    {
        int qr = t >> 1, qh2 = t & 1;
        const char* sh = (const char*)(Qh + ((size_t)(b * YD + i0 + qr)) * INNER + h * 64 + qh2 * 32);
        const char* sl = (const char*)(Ql + ((size_t)(b * YD + i0 + qr)) * INNER + h * 64 + qh2 * 32);
#pragma unroll
        for (int k = 0; k < 4; k++) {
            int c16 = qh2 * 4 + k;
            CPA16(uQh + SWZ8(qr, c16), sh + k * 16);
            CPA16(uQl + SWZ8(qr, c16), sl + k * 16);
        }
    }
    const int crow = t >> 2, cq = t & 3;
    const size_t kbase = (((size_t)b * HH + h) * WW) * 64 + (size_t)crow * 64 + cq * 16;
    const size_t vbase = ((size_t)b * INNER + h * 64 + crow) * WW + cq * 16;
#define STAGE_CHUNK(cc_) do { \
    uint32_t stg = sb + 32768 + ((cc_) & 1) * ASTAGE; \
    const char* ksh = (const char*)(Kh + kbase + (size_t)(cc_) * 64 * 64); \
    const char* ksl = (const char*)(Kl + kbase + (size_t)(cc_) * 64 * 64); \
    const char* vsh = (const char*)(Vh + vbase + (cc_) * 64); \
    const char* vsl = (const char*)(Vl + vbase + (cc_) * 64); \
    _Pragma("unroll") \
    for (int k = 0; k < 2; k++) { \
        int c16 = cq * 2 + k; \
        uint32_t sw2 = SWZ8(crow, c16); \
        CPA16(stg + sw2,         ksh + k * 16); \
        CPA16(stg + 8192 + sw2,  ksl + k * 16); \
        CPA16(stg + 16384 + sw2, vsh + k * 16); \
        CPA16(stg + 24576 + sw2, vsl + k * 16); \
    } \
} while (0)

    STAGE_CHUNK(0);
    CPA_COMMIT();

    const int arow  = lane & 15, acol8 = (lane >> 4) * 8;
    const int brow  = ((lane >> 4) & 1) * 8 + (lane & 7);
    const int bcol8 = ((lane >> 3) & 1) * 8;

    float m1 = -1e30f, m2 = -1e30f, sum1 = 0.f, sum2 = 0.f;
    float o[8][4];
#pragma unroll
    for (int dt = 0; dt < 8; dt++)
#pragma unroll
        for (int q = 0; q < 4; q++) o[dt][q] = 0.f;

    for (int c = 0; c < 4; c++) {
        CPA_WAIT0();
        __syncthreads();
        if (c + 1 < 4) { STAGE_CHUNK(c + 1); CPA_COMMIT(); }

        const uint32_t stg = sb + 32768 + (c & 1) * ASTAGE;
        const uint32_t uKh2 = stg, uKl2 = stg + 8192;
        const uint32_t uVh2 = stg + 16384, uVl2 = stg + 24576;

        float s[8][4];
#pragma unroll
        for (int nt = 0; nt < 8; nt++)
#pragma unroll
            for (int q = 0; q < 4; q++) s[nt][q] = 0.f;

#pragma unroll
        for (int kc = 0; kc < 4; kc++) {
            uint32_t ah[4], al[4];
            int ar = wid * 16 + arow;
            int ac16 = kc * 2 + (acol8 >> 3);
            uint32_t aoff = SWZ8(ar, ac16);
            LDSM_X4(ah[0], ah[1], ah[2], ah[3], uQh + aoff);
            LDSM_X4(al[0], al[1], al[2], al[3], uQl + aoff);
#pragma unroll
            for (int np = 0; np < 4; np++) {
                int br = np * 16 + brow;
                int bc16 = kc * 2 + (bcol8 >> 3);
                uint32_t boff = SWZ8(br, bc16);
                uint32_t bh[4], bl[4];
                LDSM_X4(bh[0], bh[1], bh[2], bh[3], uKh2 + boff);
                LDSM_X4(bl[0], bl[1], bl[2], bl[3], uKl2 + boff);
                mma_bf16(s[2*np],   ah, &bh[0]);
                mma_bf16(s[2*np+1], ah, &bh[2]);
                mma_bf16(s[2*np],   ah, &bl[0]);
                mma_bf16(s[2*np+1], ah, &bl[2]);
                mma_bf16(s[2*np],   al, &bh[0]);
                mma_bf16(s[2*np+1], al, &bh[2]);
            }
        }

        float cm1 = -1e30f, cm2 = -1e30f;
#pragma unroll
        for (int nt = 0; nt < 8; nt++) {
            s[nt][0] *= ASCALE; s[nt][1] *= ASCALE;
            s[nt][2] *= ASCALE; s[nt][3] *= ASCALE;
            cm1 = fmaxf(cm1, fmaxf(s[nt][0], s[nt][1]));
            cm2 = fmaxf(cm2, fmaxf(s[nt][2], s[nt][3]));
        }
        cm1 = fmaxf(cm1, __shfl_xor_sync(0xffffffffu, cm1, 1));
        cm1 = fmaxf(cm1, __shfl_xor_sync(0xffffffffu, cm1, 2));
        cm2 = fmaxf(cm2, __shfl_xor_sync(0xffffffffu, cm2, 1));
        cm2 = fmaxf(cm2, __shfl_xor_sync(0xffffffffu, cm2, 2));
        float m1n = fmaxf(m1, cm1), m2n = fmaxf(m2, cm2);
        float sc1 = __expf(m1 - m1n), sc2 = __expf(m2 - m2n);
        m1 = m1n; m2 = m2n;
#pragma unroll
        for (int dt = 0; dt < 8; dt++) {
            o[dt][0] *= sc1; o[dt][1] *= sc1;
            o[dt][2] *= sc2; o[dt][3] *= sc2;
        }
        float ls1 = 0.f, ls2 = 0.f;
#pragma unroll
        for (int nt = 0; nt < 8; nt++) {
            s[nt][0] = __expf(s[nt][0] - m1); ls1 += s[nt][0];
            s[nt][1] = __expf(s[nt][1] - m1); ls1 += s[nt][1];
            s[nt][2] = __expf(s[nt][2] - m2); ls2 += s[nt][2];
            s[nt][3] = __expf(s[nt][3] - m2); ls2 += s[nt][3];
        }
        sum1 = sum1 * sc1 + ls1;
        sum2 = sum2 * sc2 + ls2;

#pragma unroll
        for (int kk = 0; kk < 4; kk++) {
            uint32_t ph[4], pl[4];
            cvt_pair(s[2*kk][0],   s[2*kk][1],   ph[0], pl[0]);
            cvt_pair(s[2*kk][2],   s[2*kk][3],   ph[1], pl[1]);
            cvt_pair(s[2*kk+1][0], s[2*kk+1][1], ph[2], pl[2]);
            cvt_pair(s[2*kk+1][2], s[2*kk+1][3], ph[3], pl[3]);
#pragma unroll
            for (int dp = 0; dp < 4; dp++) {
                int vr = dp * 16 + brow;
                int vc16 = kk * 2 + (bcol8 >> 3);
                uint32_t voff = SWZ8(vr, vc16);
                uint32_t vh[4], vl[4];
                LDSM_X4(vh[0], vh[1], vh[2], vh[3], uVh2 + voff);
                LDSM_X4(vl[0], vl[1], vl[2], vl[3], uVl2 + voff);
                mma_bf16(o[2*dp],   ph, &vh[0]);
                mma_bf16(o[2*dp+1], ph, &vh[2]);
                mma_bf16(o[2*dp],   pl, &vh[0]);
                mma_bf16(o[2*dp+1], pl, &vh[2]);
                mma_bf16(o[2*dp],   ph, &vl[0]);
                mma_bf16(o[2*dp+1], ph, &vl[2]);
            }
        }
    }
#undef STAGE_CHUNK

    sum1 += __shfl_xor_sync(0xffffffffu, sum1, 1);
    sum1 += __shfl_xor_sync(0xffffffffu, sum1, 2);
    sum2 += __shfl_xor_sync(0xffffffffu, sum2, 1);
    sum2 += __shfl_xor_sync(0xffffffffu, sum2, 2);
    const float i1 = 1.f / sum1, i2 = 1.f / sum2;

    const int g = lane >> 2, tt = lane & 3;
    const int y = i0 + wid * 16 + g;
    size_t rb = ((size_t)b * YD + y) * INNER + h * 64;
#pragma unroll
    for (int dt = 0; dt < 8; dt++) {
        uint32_t hh, ll;
        size_t e = rb + dt * 8 + 2 * tt;
        cvt_pair(o[dt][0] * i1, o[dt][1] * i1, hh, ll);
        *(uint32_t*)&Oh[e] = hh;  *(uint32_t*)&Ol[e] = ll;
        e += (size_t)8 * INNER;
        cvt_pair(o[dt][2] * i2, o[dt][3] * i2, hh, ll);
        *(uint32_t*)&Oh[e] = hh;  *(uint32_t*)&Ol[e] = ll;
    }
}

// =====================================================================
// Out projection (NT, both phases) + residual fuse. grid(32,2,8), 256 thr.
// =====================================================================
__global__ __launch_bounds__(256, 2) void outproj_tc(
    const uint16_t* __restrict__ Wh0, const uint16_t* __restrict__ Wl0,
    const uint16_t* __restrict__ Oh0, const uint16_t* __restrict__ Ol0,
    const uint16_t* __restrict__ Wh1, const uint16_t* __restrict__ Wl1,
    const uint16_t* __restrict__ Oh1, const uint16_t* __restrict__ Ol1,
    const float* __restrict__ b0, const float* __restrict__ b1,
    const float* __restrict__ x0, const float* __restrict__ x1,
    float* __restrict__ out)
{
    extern __shared__ char smg[];
    const uint32_t sbase = smem_u32(smg);
    const int t = threadIdx.x, lane = t & 31, wid = t >> 5;
    const int wm = (wid & 1) * 64, wn = (wid >> 1) * 32;
    const int row = t >> 1, half = t & 1;
    float acc[4][4][4];
#pragma unroll
    for (int i = 0; i < 4; i++)
#pragma unroll
        for (int j = 0; j < 4; j++)
#pragma unroll
            for (int q = 0; q < 4; q++) acc[i][j][q] = 0.f;

    const int b = blockIdx.z;
    const int m0 = blockIdx.y * 128, n0 = blockIdx.x * 128;

    const size_t aOff = (size_t)(m0 + row) * INNER + half * 16;
    const size_t bOff = ((size_t)b * YD + n0 + row) * INNER + half * 16;
    const uint16_t* AH[2] = { Wh0 + aOff, Wh1 + aOff };
    const uint16_t* AL[2] = { Wl0 + aOff, Wl1 + aOff };
    const uint16_t* BH[2] = { Oh0 + bOff, Oh1 + bOff };
    const uint16_t* BL[2] = { Ol0 + bOff, Ol1 + bOff };

#define OA_H(c) (AH[(c) >> 4] + ((c) & 15) * 32)
#define OA_L(c) (AL[(c) >> 4] + ((c) & 15) * 32)
#define OB_H(c) (BH[(c) >> 4] + ((c) & 15) * 32)
#define OB_L(c) (BL[(c) >> 4] + ((c) & 15) * 32)
    PIPE_LOOP(32, OA_H, OA_L, OB_H, OB_L)
#undef OA_H
#undef OA_L
#undef OB_H
#undef OB_L

    const int g = lane >> 2, tt = lane & 3;
#pragma unroll
    for (int mt = 0; mt < 4; mt++) {
        int r = m0 + wm + mt * 16 + g;
        float biasA = 0.5f * (b0[r] + b1[r]);
        float biasB = 0.5f * (b0[r + 8] + b1[r + 8]);
#pragma unroll
        for (int nt = 0; nt < 4; nt++) {
            int cc = n0 + wn + nt * 8 + 2 * tt;
            size_t iA = ((size_t)b * DIM + r) * YD + cc;
            size_t iB = ((size_t)b * DIM + r + 8) * YD + cc;
            float2 xa = *(const float2*)&x0[iA], xb = *(const float2*)&x1[iA];
            float2 oo;
            oo.x = 0.5f * (acc[mt][nt][0] + xa.x + xb.x) + biasA;
            oo.y = 0.5f * (acc[mt][nt][1] + xa.y + xb.y) + biasA;
            *(float2*)&out[iA] = oo;
            xa = *(const float2*)&x0[iB]; xb = *(const float2*)&x1[iB];
            oo.x = 0.5f * (acc[mt][nt][2] + xa.x + xb.x) + biasB;
            oo.y = 0.5f * (acc[mt][nt][3] + xa.y + xb.y) + biasB;
            *(float2*)&out[iB] = oo;
        }
    }
}

// =====================================================================
extern "C" void kernel_launch(void* const* d_in, const int* in_sizes, int n_in,
                              void* d_out, int out_size)
{
    const float* x0    = (const float*)d_in[0];
    const float* x1    = (const float*)d_in[1];
    const float* Wq0   = (const float*)d_in[2];
    const float* Wkv0  = (const float*)d_in[3];
    const float* Wq1   = (const float*)d_in[4];
    const float* Wkv1  = (const float*)d_in[5];
    const float* Wout0 = (const float*)d_in[6];
    const float* bout0 = (const float*)d_in[7];
    const float* Wout1 = (const float*)d_in[8];
    const float* bout1 = (const float*)d_in[9];
    float* out = (float*)d_out;

    uint16_t *Wqh0, *Wql0, *Wqh1, *Wql1, *Wkvh0, *Wkvl0, *Wkvh1, *Wkvl1;
    uint16_t *Wouth0, *Woutl0, *Wouth1, *Woutl1;
    uint16_t *Xh0, *Xl0, *Xh1, *Xl1, *Xth0, *Xtl0, *Xth1, *Xtl1;
    uint16_t *Qth0, *Qtl0, *Qth1, *Qtl1;
    uint16_t *Kth0, *Ktl0, *Kth1, *Ktl1, *Vh0, *Vl0, *Vh1, *Vl1;
    uint16_t *Oh0, *Ol0, *Oh1, *Ol1;
    cudaGetSymbolAddress((void**)&Wqh0, g_Wqh0);   cudaGetSymbolAddress((void**)&Wql0, g_Wql0);
    cudaGetSymbolAddress((void**)&Wqh1, g_Wqh1);   cudaGetSymbolAddress((void**)&Wql1, g_Wql1);
    cudaGetSymbolAddress((void**)&Wkvh0, g_Wkvh0); cudaGetSymbolAddress((void**)&Wkvl0, g_Wkvl0);
    cudaGetSymbolAddress((void**)&Wkvh1, g_Wkvh1); cudaGetSymbolAddress((void**)&Wkvl1, g_Wkvl1);
    cudaGetSymbolAddress((void**)&Wouth0, g_Wouth0); cudaGetSymbolAddress((void**)&Woutl0, g_Woutl0);
    cudaGetSymbolAddress((void**)&Wouth1, g_Wouth1); cudaGetSymbolAddress((void**)&Woutl1, g_Woutl1);
    cudaGetSymbolAddress((void**)&Xh0, g_Xh0);   cudaGetSymbolAddress((void**)&Xl0, g_Xl0);
    cudaGetSymbolAddress((void**)&Xh1, g_Xh1);   cudaGetSymbolAddress((void**)&Xl1, g_Xl1);
    cudaGetSymbolAddress((void**)&Xth0, g_Xth0); cudaGetSymbolAddress((void**)&Xtl0, g_Xtl0);
    cudaGetSymbolAddress((void**)&Xth1, g_Xth1); cudaGetSymbolAddress((void**)&Xtl1, g_Xtl1);
    cudaGetSymbolAddress((void**)&Qth0, g_Qth0); cudaGetSymbolAddress((void**)&Qtl0, g_Qtl0);
    cudaGetSymbolAddress((void**)&Qth1, g_Qth1); cudaGetSymbolAddress((void**)&Qtl1, g_Qtl1);
    cudaGetSymbolAddress((void**)&Kth0, g_Kth0); cudaGetSymbolAddress((void**)&Ktl0, g_Ktl0);
    cudaGetSymbolAddress((void**)&Kth1, g_Kth1); cudaGetSymbolAddress((void**)&Ktl1, g_Ktl1);
    cudaGetSymbolAddress((void**)&Vh0, g_Vh0);   cudaGetSymbolAddress((void**)&Vl0, g_Vl0);
    cudaGetSymbolAddress((void**)&Vh1, g_Vh1);   cudaGetSymbolAddress((void**)&Vl1, g_Vl1);
    cudaGetSymbolAddress((void**)&Oh0, g_Oh0);   cudaGetSymbolAddress((void**)&Ol0, g_Ol0);
    cudaGetSymbolAddress((void**)&Oh1, g_Oh1);   cudaGetSymbolAddress((void**)&Ol1, g_Ol1);

    cudaFuncSetAttribute(proj_tc,    cudaFuncAttributeMaxDynamicSharedMemorySize, GEMM_DSMEM);
    cudaFuncSetAttribute(outproj_tc, cudaFuncAttributeMaxDynamicSharedMemorySize, GEMM_DSMEM);
    cudaFuncSetAttribute(attn_tc,    cudaFuncAttributeMaxDynamicSharedMemorySize, ATTN_DSMEM);

    cvt_all<<<dim3(8704 + 16384, 1, 1), 256>>>(
        Wq0, Wqh0, Wql0, Wq1, Wqh1, Wql1,
        Wkv0, Wkvh0, Wkvl0, Wkv1, Wkvh1, Wkvl1,
        Wout0, Wouth0, Woutl0, Wout1, Wouth1, Woutl1,
        x0, Xh0, Xl0, Xth0, Xtl0, x1, Xh1, Xl1, Xth1, Xtl1);

    proj_tc<<<dim3(2304, 1, 1), 256, GEMM_DSMEM>>>(
        Wqh0, Wql0, Xth0, Xtl0, Qth0, Qtl0,
        Wqh1, Wql1, Xth1, Xtl1, Qth1, Qtl1,
        Wkvh0, Wkvl0, Xh0, Xl0, Kth0, Ktl0, Vh0, Vl0,
        Wkvh1, Wkvl1, Xh1, Xl1, Kth1, Ktl1, Vh1, Vl1);
    attn_tc<<<dim3(YD / 128, HH, 2 * NB), 256, ATTN_DSMEM>>>(
        Qth0, Qtl0, Kth1, Ktl1, Vh1, Vl1, Oh0, Ol0,
        Qth1, Qtl1, Kth0, Ktl0, Vh0, Vl0, Oh1, Ol1);
    outproj_tc<<<dim3(YD / 128, DIM / 128, NB), 256, GEMM_DSMEM>>>(
        Wouth0, Woutl0, Oh0, Ol0, Wouth1, Woutl1, Oh1, Ol1,
        bout0, bout1, x0, x1, out);
}

// round 17
// speedup vs baseline: 1.5813x; 1.3133x over previous
#include <cuda_runtime.h>
#include <cuda_fp16.h>
#include <math.h>
#include <cstdint>

#define NB    8
#define DIM   256
#define YD    4096
#define HH    8
#define INNER 512
#define WW    256
#define ASCALE 0.125f

// ---------------- mma.sync / ldmatrix / cp.async helpers (sm_80+) ------
__device__ __forceinline__ uint32_t smem_u32(const void* p) {
    uint32_t a;
    asm("{ .reg .u64 tmp; cvta.to.shared.u64 tmp, %1; cvt.u32.u64 %0, tmp; }"
        : "=r"(a) : "l"(p));
    return a;
}
#define LDSM_X4(r0, r1, r2, r3, addr) \
    asm volatile("ldmatrix.sync.aligned.m8n8.x4.shared.b16 {%0,%1,%2,%3}, [%4];" \
        : "=r"(r0), "=r"(r1), "=r"(r2), "=r"(r3) : "r"(addr))

#define CPA16(dst, src) \
    asm volatile("cp.async.cg.shared.global [%0], [%1], 16;" :: "r"(dst), "l"(src))
#define CPA_COMMIT() asm volatile("cp.async.commit_group;")
#define CPA_WAIT1()  asm volatile("cp.async.wait_group 1;")
#define CPA_WAIT0()  asm volatile("cp.async.wait_group 0;")

__device__ __forceinline__ void mma_f16(float c[4], const uint32_t a[4], const uint32_t b[2]) {
    asm volatile("mma.sync.aligned.m16n8k16.row.col.f32.f16.f16.f32 "
        "{%0,%1,%2,%3}, {%4,%5,%6,%7}, {%8,%9}, {%0,%1,%2,%3};"
        : "+f"(c[0]), "+f"(c[1]), "+f"(c[2]), "+f"(c[3])
        : "r"(a[0]), "r"(a[1]), "r"(a[2]), "r"(a[3]), "r"(b[0]), "r"(b[1]));
}

// pack two floats into f16x2 (a in low half), round-to-nearest
__device__ __forceinline__ uint32_t cvt_h2(float a, float b) {
    uint32_t r;
    asm("cvt.rn.f16x2.f32 %0, %1, %2;" : "=r"(r) : "f"(b), "f"(a));
    return r;
}
// fp16 hi/lo split: hi = rn(a), lo = rn(a - hi)
__device__ __forceinline__ void cvt_pair_h(float a, float b, uint32_t& hi2, uint32_t& lo2) {
    hi2 = cvt_h2(a, b);
    __half2 hv = *reinterpret_cast<__half2*>(&hi2);
    float ra = a - __low2float(hv);
    float rb = b - __high2float(hv);
    lo2 = cvt_h2(ra, rb);
}

// ---------------- scratch ----------------
__device__ uint16_t g_Wq0[INNER * DIM],  g_Wq1[INNER * DIM];           // single fp16
__device__ uint16_t g_Wkv0[2 * INNER * DIM * 16], g_Wkv1[2 * INNER * DIM * 16];
__device__ uint16_t g_Wout0[DIM * INNER], g_Wout1[DIM * INNER];
__device__ uint16_t g_Xh0[NB * DIM * YD], g_Xl0[NB * DIM * YD];        // hi/lo fp16
__device__ uint16_t g_Xh1[NB * DIM * YD], g_Xl1[NB * DIM * YD];
__device__ uint16_t g_Xth0[NB * DIM * YD], g_Xtl0[NB * DIM * YD];
__device__ uint16_t g_Xth1[NB * DIM * YD], g_Xtl1[NB * DIM * YD];
__device__ uint16_t g_Qt0[(size_t)NB * YD * INNER], g_Qt1[(size_t)NB * YD * INNER];  // single
__device__ uint16_t g_Kth0[NB * HH * WW * 64], g_Ktl0[NB * HH * WW * 64];
__device__ uint16_t g_Kth1[NB * HH * WW * 64], g_Ktl1[NB * HH * WW * 64];
__device__ uint16_t g_Vh0[NB * INNER * WW], g_Vl0[NB * INNER * WW];
__device__ uint16_t g_Vh1[NB * INNER * WW], g_Vl1[NB * INNER * WW];
__device__ uint16_t g_Oh0[(size_t)NB * YD * INNER], g_Ol0[(size_t)NB * YD * INNER];
__device__ uint16_t g_Oh1[(size_t)NB * YD * INNER], g_Ol1[(size_t)NB * YD * INNER];

// =====================================================================
// Merged conversion kernel: weights -> single fp16; x -> hi/lo fp16
// in natural + transposed layouts.
// =====================================================================
__global__ __launch_bounds__(256) void cvt_all(
    const float* __restrict__ Wq0, uint16_t* __restrict__ Wq0o,
    const float* __restrict__ Wq1, uint16_t* __restrict__ Wq1o,
    const float* __restrict__ Wkv0, uint16_t* __restrict__ Wkv0o,
    const float* __restrict__ Wkv1, uint16_t* __restrict__ Wkv1o,
    const float* __restrict__ Wout0, uint16_t* __restrict__ Wout0o,
    const float* __restrict__ Wout1, uint16_t* __restrict__ Wout1o,
    const float* __restrict__ x0, uint16_t* __restrict__ Xh0, uint16_t* __restrict__ Xl0,
    uint16_t* __restrict__ Xth0, uint16_t* __restrict__ Xtl0,
    const float* __restrict__ x1, uint16_t* __restrict__ Xh1, uint16_t* __restrict__ Xl1,
    uint16_t* __restrict__ Xth1, uint16_t* __restrict__ Xtl1)
{
    __shared__ float tile[32][33];
    const int bid = blockIdx.x;
    const int t = threadIdx.x;

    if (bid < 8704) {
        const float* src; uint16_t* dst; int off;
        if (bid < 4096)      { src = Wkv0;  dst = Wkv0o;  off = bid; }
        else if (bid < 8192) { src = Wkv1;  dst = Wkv1o;  off = bid - 4096; }
        else if (bid < 8320) { src = Wq0;   dst = Wq0o;   off = bid - 8192; }
        else if (bid < 8448) { src = Wq1;   dst = Wq1o;   off = bid - 8320; }
        else if (bid < 8576) { src = Wout0; dst = Wout0o; off = bid - 8448; }
        else                 { src = Wout1; dst = Wout1o; off = bid - 8576; }
        size_t i = ((size_t)off * 256 + t) * 4;
        float4 f = *(const float4*)&src[i];
        *(uint2*)&dst[i] = make_uint2(cvt_h2(f.x, f.y), cvt_h2(f.z, f.w));
        return;
    }

    const int xb = bid - 8704;
    const int z = xb >> 10, b = z & 7;
    const int rest = xb & 1023;
    const int n0 = (rest >> 7) * 32, y0 = (rest & 127) * 32;
    const float* x = (z < 8) ? x0 : x1;
    uint16_t* Xh  = (z < 8) ? Xh0  : Xh1;
    uint16_t* Xl  = (z < 8) ? Xl0  : Xl1;
    uint16_t* Xth = (z < 8) ? Xth0 : Xth1;
    uint16_t* Xtl = (z < 8) ? Xtl0 : Xtl1;
    const int r = t >> 3, c4 = (t & 7) * 4;

    float4 f = *(const float4*)&x[((size_t)b * DIM + n0 + r) * YD + y0 + c4];
    uint32_t h0, l0, h1, l1;
    cvt_pair_h(f.x, f.y, h0, l0); cvt_pair_h(f.z, f.w, h1, l1);
    size_t nat = ((size_t)b * DIM + n0 + r) * YD + y0 + c4;
    *(uint2*)&Xh[nat] = make_uint2(h0, h1);
    *(uint2*)&Xl[nat] = make_uint2(l0, l1);
    tile[r][c4 + 0] = f.x; tile[r][c4 + 1] = f.y;
    tile[r][c4 + 2] = f.z; tile[r][c4 + 3] = f.w;
    __syncthreads();
    if (t < 128) {
        const int r2 = t >> 2, c8 = (t & 3) * 8;
        uint32_t hh[4], ll[4];
#pragma unroll
        for (int j = 0; j < 4; j++) {
            float a0 = tile[c8 + 2 * j][r2];
            float a1 = tile[c8 + 2 * j + 1][r2];
            cvt_pair_h(a0, a1, hh[j], ll[j]);
        }
        size_t tr = ((size_t)b * YD + y0 + r2) * DIM + n0 + c8;
        *(uint4*)&Xth[tr] = make_uint4(hh[0], hh[1], hh[2], hh[3]);
        *(uint4*)&Xtl[tr] = make_uint4(ll[0], ll[1], ll[2], ll[3]);
    }
}

// =====================================================================
// GEMM core: A single fp16, B hi/lo fp16, 2-pass. 128x32 tiles,
// XOR-swizzled 64B rows, 3-stage cp.async, 256 thr (8 warps of 64x32).
// =====================================================================
#define ARR   8192
#define STG   (3 * ARR)           // A, Bh, Bl = 24576 B
#define GEMM_DSMEM (3 * STG)      // 73728 B

__device__ __forceinline__ void cpa_chunk(uint32_t stage, int row, int h,
    const uint16_t* __restrict__ sA,
    const uint16_t* __restrict__ sBh, const uint16_t* __restrict__ sBl)
{
    const int s = (row >> 1) & 3;
    const uint32_t r64 = stage + (uint32_t)row * 64;
    const uint32_t u0 = (uint32_t)(((2 * h)     ^ s) << 4);
    const uint32_t u1 = (uint32_t)(((2 * h + 1) ^ s) << 4);
    CPA16(r64 + u0,           (const char*)sA);
    CPA16(r64 + u1,           (const char*)sA + 16);
    CPA16(r64 + ARR + u0,     (const char*)sBh);
    CPA16(r64 + ARR + u1,     (const char*)sBh + 16);
    CPA16(r64 + 2 * ARR + u0, (const char*)sBl);
    CPA16(r64 + 2 * ARR + u1, (const char*)sBl + 16);
}

__device__ __forceinline__ void mma_chunk2p(
    uint32_t base, float acc[4][4][4], int lane, int wm, int wn)
{
    const uint32_t aS = base, bHi = base + ARR, bLo = base + 2 * ARR;
    const int arow  = lane & 15;
    const int acol8 = (lane >> 4) * 8;
    const int brow  = ((lane >> 4) & 1) * 8 + (lane & 7);
    const int bcol8 = ((lane >> 3) & 1) * 8;
    const int sA = (arow >> 1) & 3;
    const int sB = (brow >> 1) & 3;
#pragma unroll
    for (int ks = 0; ks < 32; ks += 16) {
        const uint32_t axu = (uint32_t)(((((ks + acol8) >> 3)) ^ sA) << 4);
        const uint32_t bxu = (uint32_t)(((((ks + bcol8) >> 3)) ^ sB) << 4);
        uint32_t bh[4][2], bl[4][2];
#pragma unroll
        for (int np = 0; np < 2; np++) {
            uint32_t off = (uint32_t)(wn + np * 16 + brow) * 64 + bxu;
            LDSM_X4(bh[np*2][0], bh[np*2][1], bh[np*2+1][0], bh[np*2+1][1], bHi + off);
            LDSM_X4(bl[np*2][0], bl[np*2][1], bl[np*2+1][0], bl[np*2+1][1], bLo + off);
        }
#pragma unroll
        for (int mt = 0; mt < 4; mt++) {
            uint32_t a[4];
            uint32_t off = (uint32_t)(wm + mt * 16 + arow) * 64 + axu;
            LDSM_X4(a[0], a[1], a[2], a[3], aS + off);
#pragma unroll
            for (int nt = 0; nt < 4; nt++) mma_f16(acc[mt][nt], a, bh[nt]);
#pragma unroll
            for (int nt = 0; nt < 4; nt++) mma_f16(acc[mt][nt], a, bl[nt]);
        }
    }
}

__device__ __forceinline__ void acc_to_tile(
    float* tile, float acc[4][4][4], int lane, int wm, int wn)
{
    int g = lane >> 2, tt = lane & 3;
#pragma unroll
    for (int mt = 0; mt < 4; mt++) {
        int r = wm + mt * 16 + g;
#pragma unroll
        for (int nt = 0; nt < 4; nt++) {
            int cc = wn + nt * 8 + 2 * tt;
            tile[r * 129 + cc]           = acc[mt][nt][0];
            tile[r * 129 + cc + 1]       = acc[mt][nt][1];
            tile[(r + 8) * 129 + cc]     = acc[mt][nt][2];
            tile[(r + 8) * 129 + cc + 1] = acc[mt][nt][3];
        }
    }
}

#define PIPE_LOOP(NC, SRC_A, SRC_B_H, SRC_B_L) \
    cpa_chunk(sbase, row, half, SRC_A(0), SRC_B_H(0), SRC_B_L(0)); \
    CPA_COMMIT(); \
    cpa_chunk(sbase + STG, row, half, SRC_A(1), SRC_B_H(1), SRC_B_L(1)); \
    CPA_COMMIT(); \
    for (int c = 0; c < (NC); c++) { \
        if (c + 1 < (NC)) CPA_WAIT1(); else CPA_WAIT0(); \
        __syncthreads(); \
        if (c + 2 < (NC)) { \
            cpa_chunk(sbase + ((c + 2) % 3) * STG, row, half, \
                      SRC_A(c + 2), SRC_B_H(c + 2), SRC_B_L(c + 2)); \
            CPA_COMMIT(); \
        } \
        mma_chunk2p(sbase + (c % 3) * STG, acc, lane, wm, wn); \
    }

// =====================================================================
// Merged projection kernel: blocks [0,256) = kvproj, [256,2304) = qproj.
// =====================================================================
__global__ __launch_bounds__(256, 2) void proj_tc(
    const uint16_t* __restrict__ qA0,
    const uint16_t* __restrict__ qBh0, const uint16_t* __restrict__ qBl0,
    uint16_t* __restrict__ Q0g,
    const uint16_t* __restrict__ qA1,
    const uint16_t* __restrict__ qBh1, const uint16_t* __restrict__ qBl1,
    uint16_t* __restrict__ Q1g,
    const uint16_t* __restrict__ kA0,
    const uint16_t* __restrict__ kBh0, const uint16_t* __restrict__ kBl0,
    uint16_t* __restrict__ Kh0g, uint16_t* __restrict__ Kl0g,
    uint16_t* __restrict__ Vh0g, uint16_t* __restrict__ Vl0g,
    const uint16_t* __restrict__ kA1,
    const uint16_t* __restrict__ kBh1, const uint16_t* __restrict__ kBl1,
    uint16_t* __restrict__ Kh1g, uint16_t* __restrict__ Kl1g,
    uint16_t* __restrict__ Vh1g, uint16_t* __restrict__ Vl1g)
{
    extern __shared__ char smg[];
    const uint32_t sbase = smem_u32(smg);
    const int t = threadIdx.x, lane = t & 31, wid = t >> 5;
    const int wm = (wid & 1) * 64, wn = (wid >> 1) * 32;
    const int row = t >> 1, half = t & 1;
    float acc[4][4][4];
#pragma unroll
    for (int i = 0; i < 4; i++)
#pragma unroll
        for (int j = 0; j < 4; j++)
#pragma unroll
            for (int q = 0; q < 4; q++) acc[i][j][q] = 0.f;

    const int bid = blockIdx.x;
    if (bid < 256) {
        const int z = bid >> 4, b = z & 7;
        const int rest = bid & 15;
        const int m0 = (rest >> 1) * 128, w0 = (rest & 1) * 128;
        const int K = DIM * 16;
        const uint16_t* Aw = ((z < 8) ? kA0 : kA1) + (size_t)(m0 + row) * K + half * 16;
        const size_t bOff = (size_t)b * DIM * YD + (size_t)half * YD + (size_t)(w0 + row) * 16;
        const uint16_t* Bh = ((z < 8) ? kBh0 : kBh1) + bOff;
        const uint16_t* Bl = ((z < 8) ? kBl0 : kBl1) + bOff;

#define KA(c)   (Aw + (size_t)(c) * 32)
#define KB_H(c) (Bh + (size_t)(2 * (c)) * YD)
#define KB_L(c) (Bl + (size_t)(2 * (c)) * YD)
        PIPE_LOOP(128, KA, KB_H, KB_L)
#undef KA
#undef KB_H
#undef KB_L

        if (m0 < 512) {
            uint16_t* Kh = (z < 8) ? Kh0g : Kh1g;
            uint16_t* Kl = (z < 8) ? Kl0g : Kl1g;
            float* tile = (float*)smg;
            __syncthreads();
            acc_to_tile(tile, acc, lane, wm, wn);
            __syncthreads();
#pragma unroll
            for (int u = 0; u < 32; u++) {
                int p = u * 256 + t;
                int j = p >> 6, op = p & 63;
                int ol = 2 * op;
                float a = tile[ol * 129 + j];
                float c2 = tile[(ol + 1) * 129 + j];
                uint32_t hh, ll; cvt_pair_h(a, c2, hh, ll);
                int o = m0 + ol;
                int h = o >> 6, d = o & 63;
                size_t e = (((size_t)b * HH + h) * WW + w0 + j) * 64 + d;
                *(uint32_t*)&Kh[e] = hh;
                *(uint32_t*)&Kl[e] = ll;
            }
        } else {
            uint16_t* Vh = (z < 8) ? Vh0g : Vh1g;
            uint16_t* Vl = (z < 8) ? Vl0g : Vl1g;
            int g = lane >> 2, tt = lane & 3;
#pragma unroll
            for (int mt = 0; mt < 4; mt++) {
                int r = m0 + wm + mt * 16 + g;
#pragma unroll
                for (int nt = 0; nt < 4; nt++) {
                    int cc = w0 + wn + nt * 8 + 2 * tt;
                    uint32_t hh, ll;
                    cvt_pair_h(acc[mt][nt][0], acc[mt][nt][1], hh, ll);
                    size_t e = ((size_t)b * INNER + (r - 512)) * WW + cc;
                    *(uint32_t*)&Vh[e] = hh; *(uint32_t*)&Vl[e] = ll;
                    cvt_pair_h(acc[mt][nt][2], acc[mt][nt][3], hh, ll);
                    e = ((size_t)b * INNER + (r + 8 - 512)) * WW + cc;
                    *(uint32_t*)&Vh[e] = hh; *(uint32_t*)&Vl[e] = ll;
                }
            }
        }
    } else {
        const int qb = bid - 256;
        const int z = qb >> 7, b = z & 7;
        const int rest = qb & 127;
        const int m0 = (rest >> 5) * 128, n0 = (rest & 31) * 128;
        const uint16_t* Aw = ((z < 8) ? qA0 : qA1) + (size_t)(m0 + row) * DIM + half * 16;
        const uint16_t* Bh = ((z < 8) ? qBh0 : qBh1) + ((size_t)b * YD + n0 + row) * DIM + half * 16;
        const uint16_t* Bl = ((z < 8) ? qBl0 : qBl1) + ((size_t)b * YD + n0 + row) * DIM + half * 16;
        uint16_t* Qo = (z < 8) ? Q0g : Q1g;

#define QA(c)   (Aw + (c) * 32)
#define QB_H(c) (Bh + (c) * 32)
#define QB_L(c) (Bl + (c) * 32)
        PIPE_LOOP(8, QA, QB_H, QB_L)
#undef QA
#undef QB_H
#undef QB_L

        float* tile = (float*)smg;
        __syncthreads();
        acc_to_tile(tile, acc, lane, wm, wn);
        __syncthreads();
#pragma unroll
        for (int u = 0; u < 32; u++) {
            int p = u * 256 + t;
            int y = p >> 6, op = p & 63;
            float a = tile[(2 * op) * 129 + y];
            float c2 = tile[(2 * op + 1) * 129 + y];
            size_t e = ((size_t)b * YD + n0 + y) * INNER + m0 + 2 * op;
            *(uint32_t*)&Qo[e] = cvt_h2(a, c2);
        }
    }
}

// =====================================================================
// Attention: Q single fp16 (A), K/V hi/lo fp16 (B), 2-pass.
// cp.async staging, double-buffered K/V chunks, online softmax.
// =====================================================================
#define ATTN_DSMEM 81920
#define ASTAGE 32768
#define SWZ8(row, c16) (((uint32_t)(row)) * 128 + ((((uint32_t)(c16)) ^ ((row) & 7)) << 4))

__global__ __launch_bounds__(256, 2) void attn_tc(
    const uint16_t* __restrict__ Q0, const uint16_t* __restrict__ Kha,
    const uint16_t* __restrict__ Kla, const uint16_t* __restrict__ Vha,
    const uint16_t* __restrict__ Vla,
    uint16_t* __restrict__ Oh0, uint16_t* __restrict__ Ol0,
    const uint16_t* __restrict__ Q1, const uint16_t* __restrict__ Khb,
    const uint16_t* __restrict__ Klb, const uint16_t* __restrict__ Vhb,
    const uint16_t* __restrict__ Vlb,
    uint16_t* __restrict__ Oh1, uint16_t* __restrict__ Ol1)
{
    extern __shared__ char sm[];
    const uint32_t sb = smem_u32(sm);
    const int z = blockIdx.z, b = z & 7;
    const uint16_t* Q  = (z < NB) ? Q0 : Q1;
    const uint16_t* Kh = (z < NB) ? Kha : Khb;
    const uint16_t* Kl = (z < NB) ? Kla : Klb;
    const uint16_t* Vh = (z < NB) ? Vha : Vhb;
    const uint16_t* Vl = (z < NB) ? Vla : Vlb;
    uint16_t* Oh = (z < NB) ? Oh0 : Oh1;
    uint16_t* Ol = (z < NB) ? Ol0 : Ol1;
    const int h  = blockIdx.y;
    const int i0 = blockIdx.x * 128;

    const uint32_t uQ = sb;   // 128 rows x 128 B = 16384
    const int t = threadIdx.x, lane = t & 31, wid = t >> 5;

    {
        int qr = t >> 1, qh2 = t & 1;
        const char* sq = (const char*)(Q + ((size_t)(b * YD + i0 + qr)) * INNER + h * 64 + qh2 * 32);
#pragma unroll
        for (int k = 0; k < 4; k++) {
            int c16 = qh2 * 4 + k;
            CPA16(uQ + SWZ8(qr, c16), sq + k * 16);
        }
    }
    const int crow = t >> 2, cq = t & 3;
    const size_t kbase = (((size_t)b * HH + h) * WW) * 64 + (size_t)crow * 64 + cq * 16;
    const size_t vbase = ((size_t)b * INNER + h * 64 + crow) * WW + cq * 16;
#define STAGE_CHUNK(cc_) do { \
    uint32_t stg = sb + 16384 + ((cc_) & 1) * ASTAGE; \
    const char* ksh = (const char*)(Kh + kbase + (size_t)(cc_) * 64 * 64); \
    const char* ksl = (const char*)(Kl + kbase + (size_t)(cc_) * 64 * 64); \
    const char* vsh = (const char*)(Vh + vbase + (cc_) * 64); \
    const char* vsl = (const char*)(Vl + vbase + (cc_) * 64); \
    _Pragma("unroll") \
    for (int k = 0; k < 2; k++) { \
        int c16 = cq * 2 + k; \
        uint32_t sw2 = SWZ8(crow, c16); \
        CPA16(stg + sw2,         ksh + k * 16); \
        CPA16(stg + 8192 + sw2,  ksl + k * 16); \
        CPA16(stg + 16384 + sw2, vsh + k * 16); \
        CPA16(stg + 24576 + sw2, vsl + k * 16); \
    } \
} while (0)

    STAGE_CHUNK(0);
    CPA_COMMIT();

    const int arow  = lane & 15, acol8 = (lane >> 4) * 8;
    const int brow  = ((lane >> 4) & 1) * 8 + (lane & 7);
    const int bcol8 = ((lane >> 3) & 1) * 8;

    float m1 = -1e30f, m2 = -1e30f, sum1 = 0.f, sum2 = 0.f;
    float o[8][4];
#pragma unroll
    for (int dt = 0; dt < 8; dt++)
#pragma unroll
        for (int q = 0; q < 4; q++) o[dt][q] = 0.f;

    for (int c = 0; c < 4; c++) {
        CPA_WAIT0();
        __syncthreads();
        if (c + 1 < 4) { STAGE_CHUNK(c + 1); CPA_COMMIT(); }

        const uint32_t stg = sb + 16384 + (c & 1) * ASTAGE;
        const uint32_t uKh2 = stg, uKl2 = stg + 8192;
        const uint32_t uVh2 = stg + 16384, uVl2 = stg + 24576;

        float s[8][4];
#pragma unroll
        for (int nt = 0; nt < 8; nt++)
#pragma unroll
            for (int q = 0; q < 4; q++) s[nt][q] = 0.f;

#pragma unroll
        for (int kc = 0; kc < 4; kc++) {
            uint32_t aq[4];
            int ar = wid * 16 + arow;
            int ac16 = kc * 2 + (acol8 >> 3);
            LDSM_X4(aq[0], aq[1], aq[2], aq[3], uQ + SWZ8(ar, ac16));
#pragma unroll
            for (int np = 0; np < 4; np++) {
                int br = np * 16 + brow;
                int bc16 = kc * 2 + (bcol8 >> 3);
                uint32_t boff = SWZ8(br, bc16);
                uint32_t kh[4], kl[4];
                LDSM_X4(kh[0], kh[1], kh[2], kh[3], uKh2 + boff);
                LDSM_X4(kl[0], kl[1], kl[2], kl[3], uKl2 + boff);
                mma_f16(s[2*np],   aq, &kh[0]);
                mma_f16(s[2*np+1], aq, &kh[2]);
                mma_f16(s[2*np],   aq, &kl[0]);
                mma_f16(s[2*np+1], aq, &kl[2]);
            }
        }

        float cm1 = -1e30f, cm2 = -1e30f;
#pragma unroll
        for (int nt = 0; nt < 8; nt++) {
            s[nt][0] *= ASCALE; s[nt][1] *= ASCALE;
            s[nt][2] *= ASCALE; s[nt][3] *= ASCALE;
            cm1 = fmaxf(cm1, fmaxf(s[nt][0], s[nt][1]));
            cm2 = fmaxf(cm2, fmaxf(s[nt][2], s[nt][3]));
        }
        cm1 = fmaxf(cm1, __shfl_xor_sync(0xffffffffu, cm1, 1));
        cm1 = fmaxf(cm1, __shfl_xor_sync(0xffffffffu, cm1, 2));
        cm2 = fmaxf(cm2, __shfl_xor_sync(0xffffffffu, cm2, 1));
        cm2 = fmaxf(cm2, __shfl_xor_sync(0xffffffffu, cm2, 2));
        float m1n = fmaxf(m1, cm1), m2n = fmaxf(m2, cm2);
        float sc1 = __expf(m1 - m1n), sc2 = __expf(m2 - m2n);
        m1 = m1n; m2 = m2n;
#pragma unroll
        for (int dt = 0; dt < 8; dt++) {
            o[dt][0] *= sc1; o[dt][1] *= sc1;
            o[dt][2] *= sc2; o[dt][3] *= sc2;
        }
        float ls1 = 0.f, ls2 = 0.f;
#pragma unroll
        for (int nt = 0; nt < 8; nt++) {
            s[nt][0] = __expf(s[nt][0] - m1); ls1 += s[nt][0];
            s[nt][1] = __expf(s[nt][1] - m1); ls1 += s[nt][1];
            s[nt][2] = __expf(s[nt][2] - m2); ls2 += s[nt][2];
            s[nt][3] = __expf(s[nt][3] - m2); ls2 += s[nt][3];
        }
        sum1 = sum1 * sc1 + ls1;
        sum2 = sum2 * sc2 + ls2;

#pragma unroll
        for (int kk = 0; kk < 4; kk++) {
            uint32_t ph[4];
            ph[0] = cvt_h2(s[2*kk][0],   s[2*kk][1]);
            ph[1] = cvt_h2(s[2*kk][2],   s[2*kk][3]);
            ph[2] = cvt_h2(s[2*kk+1][0], s[2*kk+1][1]);
            ph[3] = cvt_h2(s[2*kk+1][2], s[2*kk+1][3]);
#pragma unroll
            for (int dp = 0; dp < 4; dp++) {
                int vr = dp * 16 + brow;
                int vc16 = kk * 2 + (bcol8 >> 3);
                uint32_t voff = SWZ8(vr, vc16);
                uint32_t vh[4], vl[4];
                LDSM_X4(vh[0], vh[1], vh[2], vh[3], uVh2 + voff);
                LDSM_X4(vl[0], vl[1], vl[2], vl[3], uVl2 + voff);
                mma_f16(o[2*dp],   ph, &vh[0]);
                mma_f16(o[2*dp+1], ph, &vh[2]);
                mma_f16(o[2*dp],   ph, &vl[0]);
                mma_f16(o[2*dp+1], ph, &vl[2]);
            }
        }
    }
#undef STAGE_CHUNK

    sum1 += __shfl_xor_sync(0xffffffffu, sum1, 1);
    sum1 += __shfl_xor_sync(0xffffffffu, sum1, 2);
    sum2 += __shfl_xor_sync(0xffffffffu, sum2, 1);
    sum2 += __shfl_xor_sync(0xffffffffu, sum2, 2);
    const float i1 = 1.f / sum1, i2 = 1.f / sum2;

    const int g = lane >> 2, tt = lane & 3;
    const int y = i0 + wid * 16 + g;
    size_t rb = ((size_t)b * YD + y) * INNER + h * 64;
#pragma unroll
    for (int dt = 0; dt < 8; dt++) {
        uint32_t hh, ll;
        size_t e = rb + dt * 8 + 2 * tt;
        cvt_pair_h(o[dt][0] * i1, o[dt][1] * i1, hh, ll);
        *(uint32_t*)&Oh[e] = hh;  *(uint32_t*)&Ol[e] = ll;
        e += (size_t)8 * INNER;
        cvt_pair_h(o[dt][2] * i2, o[dt][3] * i2, hh, ll);
        *(uint32_t*)&Oh[e] = hh;  *(uint32_t*)&Ol[e] = ll;
    }
}

// =====================================================================
// Out projection: A = Wout single, B = O hi/lo; + residual fuse.
// =====================================================================
__global__ __launch_bounds__(256, 2) void outproj_tc(
    const uint16_t* __restrict__ W0, const uint16_t* __restrict__ Oh0,
    const uint16_t* __restrict__ Ol0,
    const uint16_t* __restrict__ W1, const uint16_t* __restrict__ Oh1,
    const uint16_t* __restrict__ Ol1,
    const float* __restrict__ b0, const float* __restrict__ b1,
    const float* __restrict__ x0, const float* __restrict__ x1,
    float* __restrict__ out)
{
    extern __shared__ char smg[];
    const uint32_t sbase = smem_u32(smg);
    const int t = threadIdx.x, lane = t & 31, wid = t >> 5;
    const int wm = (wid & 1) * 64, wn = (wid >> 1) * 32;
    const int row = t >> 1, half = t & 1;
    float acc[4][4][4];
#pragma unroll
    for (int i = 0; i < 4; i++)
#pragma unroll
        for (int j = 0; j < 4; j++)
#pragma unroll
            for (int q = 0; q < 4; q++) acc[i][j][q] = 0.f;

    const int b = blockIdx.z;
    const int m0 = blockIdx.y * 128, n0 = blockIdx.x * 128;

    const size_t aOff = (size_t)(m0 + row) * INNER + half * 16;
    const size_t bOff = ((size_t)b * YD + n0 + row) * INNER + half * 16;
    const uint16_t* AW[2] = { W0 + aOff, W1 + aOff };
    const uint16_t* BH[2] = { Oh0 + bOff, Oh1 + bOff };
    const uint16_t* BL[2] = { Ol0 + bOff, Ol1 + bOff };

#define OA(c)   (AW[(c) >> 4] + ((c) & 15) * 32)
#define OB_H(c) (BH[(c) >> 4] + ((c) & 15) * 32)
#define OB_L(c) (BL[(c) >> 4] + ((c) & 15) * 32)
    PIPE_LOOP(32, OA, OB_H, OB_L)
#undef OA
#undef OB_H
#undef OB_L

    const int g = lane >> 2, tt = lane & 3;
#pragma unroll
    for (int mt = 0; mt < 4; mt++) {
        int r = m0 + wm + mt * 16 + g;
        float biasA = 0.5f * (b0[r] + b1[r]);
        float biasB = 0.5f * (b0[r + 8] + b1[r + 8]);
#pragma unroll
        for (int nt = 0; nt < 4; nt++) {
            int cc = n0 + wn + nt * 8 + 2 * tt;
            size_t iA = ((size_t)b * DIM + r) * YD + cc;
            size_t iB = ((size_t)b * DIM + r + 8) * YD + cc;
            float2 xa = *(const float2*)&x0[iA], xb = *(const float2*)&x1[iA];
            float2 oo;
            oo.x = 0.5f * (acc[mt][nt][0] + xa.x + xb.x) + biasA;
            oo.y = 0.5f * (acc[mt][nt][1] + xa.y + xb.y) + biasA;
            *(float2*)&out[iA] = oo;
            xa = *(const float2*)&x0[iB]; xb = *(const float2*)&x1[iB];
            oo.x = 0.5f * (acc[mt][nt][2] + xa.x + xb.x) + biasB;
            oo.y = 0.5f * (acc[mt][nt][3] + xa.y + xb.y) + biasB;
            *(float2*)&out[iB] = oo;
        }
    }
}

// =====================================================================
extern "C" void kernel_launch(void* const* d_in, const int* in_sizes, int n_in,
                              void* d_out, int out_size)
{
    const float* x0    = (const float*)d_in[0];
    const float* x1    = (const float*)d_in[1];
    const float* Wq0   = (const float*)d_in[2];
    const float* Wkv0  = (const float*)d_in[3];
    const float* Wq1   = (const float*)d_in[4];
    const float* Wkv1  = (const float*)d_in[5];
    const float* Wout0 = (const float*)d_in[6];
    const float* bout0 = (const float*)d_in[7];
    const float* Wout1 = (const float*)d_in[8];
    const float* bout1 = (const float*)d_in[9];
    float* out = (float*)d_out;

    uint16_t *Wq0p, *Wq1p, *Wkv0p, *Wkv1p, *Wout0p, *Wout1p;
    uint16_t *Xh0, *Xl0, *Xh1, *Xl1, *Xth0, *Xtl0, *Xth1, *Xtl1;
    uint16_t *Qt0, *Qt1;
    uint16_t *Kth0, *Ktl0, *Kth1, *Ktl1, *Vh0, *Vl0, *Vh1, *Vl1;
    uint16_t *Oh0, *Ol0, *Oh1, *Ol1;
    cudaGetSymbolAddress((void**)&Wq0p, g_Wq0);   cudaGetSymbolAddress((void**)&Wq1p, g_Wq1);
    cudaGetSymbolAddress((void**)&Wkv0p, g_Wkv0); cudaGetSymbolAddress((void**)&Wkv1p, g_Wkv1);
    cudaGetSymbolAddress((void**)&Wout0p, g_Wout0); cudaGetSymbolAddress((void**)&Wout1p, g_Wout1);
    cudaGetSymbolAddress((void**)&Xh0, g_Xh0);   cudaGetSymbolAddress((void**)&Xl0, g_Xl0);
    cudaGetSymbolAddress((void**)&Xh1, g_Xh1);   cudaGetSymbolAddress((void**)&Xl1, g_Xl1);
    cudaGetSymbolAddress((void**)&Xth0, g_Xth0); cudaGetSymbolAddress((void**)&Xtl0, g_Xtl0);
    cudaGetSymbolAddress((void**)&Xth1, g_Xth1); cudaGetSymbolAddress((void**)&Xtl1, g_Xtl1);
    cudaGetSymbolAddress((void**)&Qt0, g_Qt0);   cudaGetSymbolAddress((void**)&Qt1, g_Qt1);
    cudaGetSymbolAddress((void**)&Kth0, g_Kth0); cudaGetSymbolAddress((void**)&Ktl0, g_Ktl0);
    cudaGetSymbolAddress((void**)&Kth1, g_Kth1); cudaGetSymbolAddress((void**)&Ktl1, g_Ktl1);
    cudaGetSymbolAddress((void**)&Vh0, g_Vh0);   cudaGetSymbolAddress((void**)&Vl0, g_Vl0);
    cudaGetSymbolAddress((void**)&Vh1, g_Vh1);   cudaGetSymbolAddress((void**)&Vl1, g_Vl1);
    cudaGetSymbolAddress((void**)&Oh0, g_Oh0);   cudaGetSymbolAddress((void**)&Ol0, g_Ol0);
    cudaGetSymbolAddress((void**)&Oh1, g_Oh1);   cudaGetSymbolAddress((void**)&Ol1, g_Ol1);

    cudaFuncSetAttribute(proj_tc,    cudaFuncAttributeMaxDynamicSharedMemorySize, GEMM_DSMEM);
    cudaFuncSetAttribute(outproj_tc, cudaFuncAttributeMaxDynamicSharedMemorySize, GEMM_DSMEM);
    cudaFuncSetAttribute(attn_tc,    cudaFuncAttributeMaxDynamicSharedMemorySize, ATTN_DSMEM);

    cvt_all<<<dim3(8704 + 16384, 1, 1), 256>>>(
        Wq0, Wq0p, Wq1, Wq1p, Wkv0, Wkv0p, Wkv1, Wkv1p,
        Wout0, Wout0p, Wout1, Wout1p,
        x0, Xh0, Xl0, Xth0, Xtl0, x1, Xh1, Xl1, Xth1, Xtl1);

    proj_tc<<<dim3(2304, 1, 1), 256, GEMM_DSMEM>>>(
        Wq0p, Xth0, Xtl0, Qt0,
        Wq1p, Xth1, Xtl1, Qt1,
        Wkv0p, Xh0, Xl0, Kth0, Ktl0, Vh0, Vl0,
        Wkv1p, Xh1, Xl1, Kth1, Ktl1, Vh1, Vl1);
    // stream0 attends KV of stream1 and vice versa
    attn_tc<<<dim3(YD / 128, HH, 2 * NB), 256, ATTN_DSMEM>>>(
        Qt0, Kth1, Ktl1, Vh1, Vl1, Oh0, Ol0,
        Qt1, Kth0, Ktl0, Vh0, Vl0, Oh1, Ol1);
    outproj_tc<<<dim3(YD / 128, DIM / 128, NB), 256, GEMM_DSMEM>>>(
        Wout0p, Oh0, Ol0, Wout1p, Oh1, Ol1,
        bout0, bout1, x0, x1, out);
}